// round 5
// baseline (speedup 1.0000x reference)
#include <cuda_runtime.h>
#include <stdint.h>
#include <stddef.h>

// Problem constants
#define DRUGN   100000
#define DISN    100000
#define NRD     200000
#define HIDN    64
#define EDG_RR  1600000
#define EDG_DD  1600000
#define EDG_RD  3200000
#define HBITS   6400000u     // flat-index offset of dis rows (100000*64)
#define EPSF    0.1f

// Output packing (float32), tuple order:
// drugE, disE, drugAll, disAll, rd_drug, rd_dis, meta_reg_loss, rd_stack
static const size_t OFF_DRUGE   = 0;
static const size_t OFF_DISE    = 6400000;
static const size_t OFF_DRUGALL = 12800000;
static const size_t OFF_DISALL  = 19200000;
static const size_t OFF_RDDRUG  = 25600000;
static const size_t OFF_RDDIS   = 32000000;
static const size_t OFF_LOSS    = 38400000;
static const size_t OFF_RDSTACK = 38400001;

// Scratch (static device arrays: no runtime allocation allowed)
__device__ float g_G  [(size_t)NRD * HIDN];   // gated init (rr0 | dd0)
__device__ float g_cur[(size_t)NRD * HIDN];   // current rd features
__device__ float g_P  [(size_t)NRD * HIDN];   // prop output (d0 | s0)
__device__ float g_R  [(size_t)NRD * HIDN];   // prop output r0
__device__ float g_deg[800000];               // degree sums: 6 slices
__device__ float g_w  [6400000];              // normalized edge weights (rr|dd|rd)

// deg slices
#define DRR_R 0
#define DRR_C 100000
#define DDD_R 200000
#define DDD_C 300000
#define DRD_R 400000
#define DRD_C 600000
// weight slices
#define WRR 0
#define WDD 1600000
#define WRD 3200000

// ---------------- threefry2x32 (bit-exact JAX core) ----------------
#define TFROUND(x0,x1,r) { x0 += x1; x1 = __funnelshift_l(x1,x1,r); x1 ^= x0; }

__device__ __forceinline__ void tf2x32(uint32_t k0, uint32_t k1, uint32_t &x0, uint32_t &x1) {
    uint32_t k2 = k0 ^ k1 ^ 0x1BD11BDAu;
    x0 += k0; x1 += k1;
    TFROUND(x0,x1,13) TFROUND(x0,x1,15) TFROUND(x0,x1,26) TFROUND(x0,x1,6)
    x0 += k1; x1 += k2 + 1u;
    TFROUND(x0,x1,17) TFROUND(x0,x1,29) TFROUND(x0,x1,16) TFROUND(x0,x1,24)
    x0 += k2; x1 += k0 + 2u;
    TFROUND(x0,x1,13) TFROUND(x0,x1,15) TFROUND(x0,x1,26) TFROUND(x0,x1,6)
    x0 += k0; x1 += k1 + 3u;
    TFROUND(x0,x1,17) TFROUND(x0,x1,29) TFROUND(x0,x1,16) TFROUND(x0,x1,24)
    x0 += k1; x1 += k2 + 4u;
    TFROUND(x0,x1,13) TFROUND(x0,x1,15) TFROUND(x0,x1,26) TFROUND(x0,x1,6)
    x0 += k2; x1 += k0 + 5u;
}

// Partitionable-threefry random bits for flat element index f (< 2^32):
// counter = (0, f); 32-bit output = y0 ^ y1.
__device__ __forceinline__ uint32_t tf_bits32(uint32_t k0, uint32_t k1, uint32_t f) {
    uint32_t x0 = 0u, x1 = f;
    tf2x32(k0, k1, x0, x1);
    return x0 ^ x1;
}

__device__ __forceinline__ float u01(uint32_t b) {
    return __uint_as_float((b >> 9) | 0x3f800000u) - 1.0f;
}
__device__ __forceinline__ float fsgn(float x) {
    return (x > 0.f) ? 1.f : ((x < 0.f) ? -1.f : 0.f);
}

// ---------------- degree accumulation ----------------
__global__ void deg_kernel(const int* __restrict__ er, const int* __restrict__ ec,
                           const float* __restrict__ ev, int E,
                           float* __restrict__ dr, float* __restrict__ dc) {
    int e = blockIdx.x * blockDim.x + threadIdx.x;
    if (e >= E) return;
    float v = ev[e];
    atomicAdd(&dr[er[e]], v);
    atomicAdd(&dc[ec[e]], v);
}

// ---------------- per-edge normalized weight ----------------
__global__ void wnorm_kernel(const int* __restrict__ er, const int* __restrict__ ec,
                             const float* __restrict__ ev,
                             const float* __restrict__ dr, const float* __restrict__ dc,
                             float* __restrict__ w, int E) {
    int e = blockIdx.x * blockDim.x + threadIdx.x;
    if (e >= E) return;
    w[e] = ev[e] * rsqrtf(fmaxf(dr[er[e]] * dc[ec[e]], 1e-12f));
}

// ---------------- init: gated GEMM + buffer init ----------------
// 4 nodes per block, 64 threads per node; thread computes one output column.
__global__ void init_kernel(const float* __restrict__ de, const float* __restrict__ se,
                            const float* __restrict__ Wr, const float* __restrict__ br,
                            const float* __restrict__ Wd, const float* __restrict__ bd,
                            float* __restrict__ G, float* __restrict__ cur,
                            float* __restrict__ eD, float* __restrict__ eS,
                            float* __restrict__ rds) {
    __shared__ float sW[64 * 64];
    __shared__ float sb[64];
    __shared__ float sx[4][64];
    bool isDis = (blockIdx.x >= (DRUGN / 4));
    const float* W = isDis ? Wd : Wr;
    const float* b = isDis ? bd : br;
    for (int t = threadIdx.x; t < 4096; t += blockDim.x) sW[t] = W[t];
    if (threadIdx.x < 64) sb[threadIdx.x] = b[threadIdx.x];

    int local = threadIdx.x >> 6;             // 0..3
    int j     = threadIdx.x & 63;             // output column
    int n = blockIdx.x * 4 + local;           // node 0..NRD-1
    const float* emb = isDis ? se : de;
    size_t lrow = isDis ? (size_t)(n - DRUGN) * 64 : (size_t)n * 64;
    sx[local][j] = emb[lrow + j];
    __syncthreads();

    float z = sb[j];
#pragma unroll 16
    for (int k = 0; k < 64; k++) z = fmaf(sx[local][k], sW[k * 64 + j], z);
    float x = sx[local][j];
    float g = x * (1.0f / (1.0f + expf(-z)));

    size_t base = (size_t)n * 64;
    G[base + j]   = g;
    cur[base + j] = x;
    rds[(size_t)n * 256 + j] = x;
    if (!isDis) eD[base + j] = g;
    else        eS[(size_t)(n - DRUGN) * 64 + j] = g;
}

// ---------------- SpMM: dst[row] += w[e] * src[col] ----------------
// 16 threads per edge (one float4 each); edge metadata loaded once per
// 16-lane group (lane 0 / lane 16) and shfl-broadcast.
__global__ void spmm_kernel(const int* __restrict__ er, const int* __restrict__ ec,
                            const float* __restrict__ w,
                            const float* __restrict__ src, float* __restrict__ dst,
                            int E, int roff, int coff) {
    int t = blockIdx.x * blockDim.x + threadIdx.x;
    int e = t >> 4;
    int lane = threadIdx.x & 31;
    int s = lane & 15;
    bool valid = (e < E);
    int r = 0, c = 0; float wv = 0.f;
    if (valid && s == 0) { r = er[e]; c = ec[e]; wv = w[e]; }
    int srcLane = lane & 16;
    r  = __shfl_sync(0xffffffffu, r,  srcLane);
    c  = __shfl_sync(0xffffffffu, c,  srcLane);
    wv = __shfl_sync(0xffffffffu, wv, srcLane);
    if (!valid) return;
    const float4 v = *((const float4*)(src + (size_t)(c + coff) * 64) + s);
    float4 out;
    out.x = v.x * wv; out.y = v.y * wv; out.z = v.z * wv; out.w = v.w * wv;
    float* p = dst + (size_t)(r + roff) * 64 + s * 4;
    asm volatile("red.global.add.v4.f32 [%0], {%1,%2,%3,%4};"
                 :: "l"(p), "f"(out.x), "f"(out.y), "f"(out.z), "f"(out.w) : "memory");
}

// ---------------- per-layer combine: noise + norms + updates ----------------
// One warp handles drug row n and dis row n+DRUGN. Noise per element f:
// partitionable threefry, counter (0, f), bits = y0 ^ y1.
__global__ void combine_kernel(const float* __restrict__ P, const float* __restrict__ R,
                               float* __restrict__ cur, float* __restrict__ eD,
                               float* __restrict__ eS, float* __restrict__ rds,
                               int layer, uint32_t k0, uint32_t k1) {
    int gw = (blockIdx.x * blockDim.x + threadIdx.x) >> 5;
    int lane = threadIdx.x & 31;
    if (gw >= DRUGN) return;
    size_t bn = (size_t)gw * 64;
    size_t bm = (size_t)(gw + DRUGN) * 64;

    uint32_t f0 = (uint32_t)gw * 64u + (uint32_t)lane;
    float un0 = u01(tf_bits32(k0, k1, f0));                 // drug row, col lane
    float un1 = u01(tf_bits32(k0, k1, f0 + 32u));           // drug row, col lane+32
    float um0 = u01(tf_bits32(k0, k1, f0 + HBITS));         // dis row,  col lane
    float um1 = u01(tf_bits32(k0, k1, f0 + 32u + HBITS));   // dis row,  col lane+32

    float sn = fmaf(un0, un0, un1 * un1);
    float sm = fmaf(um0, um0, um1 * um1);
#pragma unroll
    for (int o = 16; o; o >>= 1) {
        sn += __shfl_xor_sync(0xffffffffu, sn, o);
        sm += __shfl_xor_sync(0xffffffffu, sm, o);
    }
    float scn = EPSF / fmaxf(sqrtf(sn), 1e-12f);
    float scm = EPSF / fmaxf(sqrtf(sm), 1e-12f);

    float rn0 = R[bn + lane], rn1 = R[bn + 32 + lane];
    float rm0 = R[bm + lane], rm1 = R[bm + 32 + lane];
    rn0 += fsgn(rn0) * un0 * scn;  rn1 += fsgn(rn1) * un1 * scn;
    rm0 += fsgn(rm0) * um0 * scm;  rm1 += fsgn(rm1) * um1 * scm;

    float qn = fmaf(rn0, rn0, rn1 * rn1);
    float qm = fmaf(rm0, rm0, rm1 * rm1);
#pragma unroll
    for (int o = 16; o; o >>= 1) {
        qn += __shfl_xor_sync(0xffffffffu, qn, o);
        qm += __shfl_xor_sync(0xffffffffu, qm, o);
    }
    float inr = 1.f / fmaxf(sqrtf(qn), 1e-12f);
    float imr = 1.f / fmaxf(sqrtf(qm), 1e-12f);

    size_t snb = (size_t)gw * 256 + (size_t)(layer + 1) * 64;
    size_t smb = (size_t)(gw + DRUGN) * 256 + (size_t)(layer + 1) * 64;
    rds[snb + lane] = rn0 * inr;  rds[snb + 32 + lane] = rn1 * inr;
    rds[smb + lane] = rm0 * imr;  rds[smb + 32 + lane] = rm1 * imr;

    float pn0 = P[bn + lane], pn1 = P[bn + 32 + lane];
    float pm0 = P[bm + lane], pm1 = P[bm + 32 + lane];
    cur[bn + lane]      = 0.5f * pn0 + 0.5f * rn0;
    cur[bn + 32 + lane] = 0.5f * pn1 + 0.5f * rn1;
    cur[bm + lane]      = 0.5f * pm0 + 0.5f * rm0;
    cur[bm + 32 + lane] = 0.5f * pm1 + 0.5f * rm1;

    float tn = fmaf(pn0, pn0, pn1 * pn1);
    float tm = fmaf(pm0, pm0, pm1 * pm1);
#pragma unroll
    for (int o = 16; o; o >>= 1) {
        tn += __shfl_xor_sync(0xffffffffu, tn, o);
        tm += __shfl_xor_sync(0xffffffffu, tm, o);
    }
    float ipn = 1.f / fmaxf(sqrtf(tn), 1e-12f);
    float ipm = 1.f / fmaxf(sqrtf(tm), 1e-12f);

    eD[bn + lane]      += pn0 * ipn;
    eD[bn + 32 + lane] += pn1 * ipn;
    size_t bs = (size_t)gw * 64;
    eS[bs + lane]      += pm0 * ipm;
    eS[bs + 32 + lane] += pm1 * ipm;
}

// ---------------- final: scale means, combine with embeddings ----------------
__global__ void final_kernel(const float* __restrict__ de, const float* __restrict__ se,
                             float* __restrict__ out) {
    size_t i = (size_t)blockIdx.x * blockDim.x + threadIdx.x;
    if (i == 0) out[OFF_LOSS] = 0.f;
    if (i < 6400000) {
        float E = out[OFF_DRUGE + i] * 0.25f;
        float emb = de[i];
        out[OFF_DRUGE + i] = E;
        out[OFF_DRUGALL + i] = 0.5f * emb + 0.5f * E;
        out[OFF_RDDRUG + i] = emb;
    } else if (i < 12800000) {
        size_t j = i - 6400000;
        float E = out[OFF_DISE + j] * 0.25f;
        float emb = se[j];
        out[OFF_DISE + j] = E;
        out[OFF_DISALL + j] = 0.5f * emb + 0.5f * E;
        out[OFF_RDDIS + j] = emb;
    }
}

// ---------------- host-side threefry for key folding ----------------
static inline void tf_host(uint32_t k0, uint32_t k1, uint32_t* px0, uint32_t* px1) {
    uint32_t x0 = *px0, x1 = *px1;
    uint32_t k2 = k0 ^ k1 ^ 0x1BD11BDAu;
#define HROT(r) { x0 += x1; x1 = (x1 << r) | (x1 >> (32 - r)); x1 ^= x0; }
    x0 += k0; x1 += k1;
    HROT(13) HROT(15) HROT(26) HROT(6)
    x0 += k1; x1 += k2 + 1u;
    HROT(17) HROT(29) HROT(16) HROT(24)
    x0 += k2; x1 += k0 + 2u;
    HROT(13) HROT(15) HROT(26) HROT(6)
    x0 += k0; x1 += k1 + 3u;
    HROT(17) HROT(29) HROT(16) HROT(24)
    x0 += k1; x1 += k2 + 4u;
    HROT(13) HROT(15) HROT(26) HROT(6)
    x0 += k2; x1 += k0 + 5u;
#undef HROT
    *px0 = x0; *px1 = x1;
}

extern "C" void kernel_launch(void* const* d_in, const int* in_sizes, int n_in,
                              void* d_out, int out_size) {
    const float* drug_emb = (const float*)d_in[0];
    const float* dis_emb  = (const float*)d_in[1];
    const float* Wr = (const float*)d_in[2];
    const float* br = (const float*)d_in[3];
    const float* Wd = (const float*)d_in[4];
    const float* bd = (const float*)d_in[5];
    const int*   rr_row = (const int*)d_in[6];
    const int*   rr_col = (const int*)d_in[7];
    const float* rr_val = (const float*)d_in[8];
    const int*   dd_row = (const int*)d_in[9];
    const int*   dd_col = (const int*)d_in[10];
    const float* dd_val = (const float*)d_in[11];
    const int*   rd_row = (const int*)d_in[12];
    const int*   rd_col = (const int*)d_in[13];
    const float* rd_val = (const float*)d_in[14];
    float* out = (float*)d_out;

    float *G, *cur, *P, *R, *deg, *w;
    cudaGetSymbolAddress((void**)&G,   g_G);
    cudaGetSymbolAddress((void**)&cur, g_cur);
    cudaGetSymbolAddress((void**)&P,   g_P);
    cudaGetSymbolAddress((void**)&R,   g_R);
    cudaGetSymbolAddress((void**)&deg, g_deg);
    cudaGetSymbolAddress((void**)&w,   g_w);

    const size_t featBytes = (size_t)NRD * HIDN * sizeof(float);

    // Degrees + normalized edge weights (graph-invariant across layers)
    cudaMemsetAsync(deg, 0, 800000 * sizeof(float), 0);
    deg_kernel<<<(EDG_RR + 255) / 256, 256>>>(rr_row, rr_col, rr_val, EDG_RR, deg + DRR_R, deg + DRR_C);
    deg_kernel<<<(EDG_DD + 255) / 256, 256>>>(dd_row, dd_col, dd_val, EDG_DD, deg + DDD_R, deg + DDD_C);
    deg_kernel<<<(EDG_RD + 255) / 256, 256>>>(rd_row, rd_col, rd_val, EDG_RD, deg + DRD_R, deg + DRD_C);
    wnorm_kernel<<<(EDG_RR + 255) / 256, 256>>>(rr_row, rr_col, rr_val, deg + DRR_R, deg + DRR_C, w + WRR, EDG_RR);
    wnorm_kernel<<<(EDG_DD + 255) / 256, 256>>>(dd_row, dd_col, dd_val, deg + DDD_R, deg + DDD_C, w + WDD, EDG_DD);
    wnorm_kernel<<<(EDG_RD + 255) / 256, 256>>>(rd_row, rd_col, rd_val, deg + DRD_R, deg + DRD_C, w + WRD, EDG_RD);

    // Init: gates, cur = raw emb, rd_stack slice 0, drugE/disE accumulators
    init_kernel<<<NRD / 4, 256>>>(drug_emb, dis_emb, Wr, br, Wd, bd,
                                  G, cur, out + OFF_DRUGE, out + OFF_DISE, out + OFF_RDSTACK);

    for (int i = 0; i < 3; i++) {
        // fold_in(key(1), i): threefry2x32(key=(0,1), count=(0,i))
        uint32_t lk0 = 0u, lk1 = (uint32_t)i;
        tf_host(0u, 1u, &lk0, &lk1);

        cudaMemsetAsync(P, 0, featBytes, 0);
        cudaMemsetAsync(R, 0, featBytes, 0);

        const float* srcG = (i == 0) ? G : cur;
        spmm_kernel<<<(EDG_RR * 16 + 255) / 256, 256>>>(rr_row, rr_col, w + WRR, srcG, P, EDG_RR, 0, 0);
        spmm_kernel<<<(EDG_DD * 16 + 255) / 256, 256>>>(dd_row, dd_col, w + WDD, srcG, P, EDG_DD, DRUGN, DRUGN);
        spmm_kernel<<<(EDG_RD * 16 + 255) / 256, 256>>>(rd_row, rd_col, w + WRD, cur, R, EDG_RD, 0, 0);

        combine_kernel<<<(DRUGN * 32) / 256, 256>>>(P, R, cur,
            out + OFF_DRUGE, out + OFF_DISE, out + OFF_RDSTACK, i, lk0, lk1);
    }

    final_kernel<<<(12800000 + 255) / 256, 256>>>(drug_emb, dis_emb, out);
}

// round 7
// speedup vs baseline: 1.1802x; 1.1802x over previous
#include <cuda_runtime.h>
#include <stdint.h>
#include <stddef.h>

// Problem constants
#define DRUGN   100000
#define DISN    100000
#define NRD     200000
#define HIDN    64
#define EDG_RR  1600000
#define EDG_DD  1600000
#define EDG_RD  3200000
#define E_TOT   6400000
#define HBITS   6400000u     // flat-index offset of dis rows (100000*64)
#define EPSF    0.1f

// Output packing (float32), tuple order:
// drugE, disE, drugAll, disAll, rd_drug, rd_dis, meta_reg_loss, rd_stack
static const size_t OFF_DRUGE   = 0;
static const size_t OFF_DISE    = 6400000;
static const size_t OFF_DRUGALL = 12800000;
static const size_t OFF_DISALL  = 19200000;
static const size_t OFF_RDDRUG  = 25600000;
static const size_t OFF_RDDIS   = 32000000;
static const size_t OFF_LOSS    = 38400000;
static const size_t OFF_RDSTACK = 38400001;

// Scratch (static device arrays: no runtime allocation allowed)
__device__ float g_G  [(size_t)NRD * HIDN];   // gated init (rr0 | dd0)
__device__ float g_cur[(size_t)NRD * HIDN];   // current rd features
__device__ float g_P  [(size_t)NRD * HIDN];   // prop output (d0 | s0)
__device__ float g_R  [(size_t)NRD * HIDN];   // prop output r0
__device__ float g_deg[800000];               // degree sums: 6 slices
__device__ int2  g_csr[E_TOT];                // packed (col, w) per edge, CSR order
__device__ int   g_cnt[400000];               // row counts: rr|dd|rd
__device__ int   g_rptr[400003];              // row pointers: rr|dd|rd (each +1)
__device__ int   g_cursor[400003];            // scatter cursors (copy of rptr)

// deg slices
#define DRR_R 0
#define DRR_C 100000
#define DDD_R 200000
#define DDD_C 300000
#define DRD_R 400000
#define DRD_C 600000
// count slices
#define CNT_RR 0
#define CNT_DD 100000
#define CNT_RD 200000
// rowptr slices
#define RP_RR 0
#define RP_DD 100001
#define RP_RD 200002
// edge-base slices in g_csr
#define EB_RR 0
#define EB_DD 1600000
#define EB_RD 3200000

// ---------------- threefry2x32 (bit-exact JAX core) ----------------
#define TFROUND(x0,x1,r) { x0 += x1; x1 = __funnelshift_l(x1,x1,r); x1 ^= x0; }

__device__ __forceinline__ void tf2x32(uint32_t k0, uint32_t k1, uint32_t &x0, uint32_t &x1) {
    uint32_t k2 = k0 ^ k1 ^ 0x1BD11BDAu;
    x0 += k0; x1 += k1;
    TFROUND(x0,x1,13) TFROUND(x0,x1,15) TFROUND(x0,x1,26) TFROUND(x0,x1,6)
    x0 += k1; x1 += k2 + 1u;
    TFROUND(x0,x1,17) TFROUND(x0,x1,29) TFROUND(x0,x1,16) TFROUND(x0,x1,24)
    x0 += k2; x1 += k0 + 2u;
    TFROUND(x0,x1,13) TFROUND(x0,x1,15) TFROUND(x0,x1,26) TFROUND(x0,x1,6)
    x0 += k0; x1 += k1 + 3u;
    TFROUND(x0,x1,17) TFROUND(x0,x1,29) TFROUND(x0,x1,16) TFROUND(x0,x1,24)
    x0 += k1; x1 += k2 + 4u;
    TFROUND(x0,x1,13) TFROUND(x0,x1,15) TFROUND(x0,x1,26) TFROUND(x0,x1,6)
    x0 += k2; x1 += k0 + 5u;
}

// Partitionable-threefry random bits for flat element index f (< 2^32):
// counter = (0, f); 32-bit output = y0 ^ y1.
__device__ __forceinline__ uint32_t tf_bits32(uint32_t k0, uint32_t k1, uint32_t f) {
    uint32_t x0 = 0u, x1 = f;
    tf2x32(k0, k1, x0, x1);
    return x0 ^ x1;
}

__device__ __forceinline__ float u01(uint32_t b) {
    return __uint_as_float((b >> 9) | 0x3f800000u) - 1.0f;
}
__device__ __forceinline__ float fsgn(float x) {
    return (x > 0.f) ? 1.f : ((x < 0.f) ? -1.f : 0.f);
}

// ---------------- degree accumulation ----------------
__global__ void deg_kernel(const int* __restrict__ er, const int* __restrict__ ec,
                           const float* __restrict__ ev, int E,
                           float* __restrict__ dr, float* __restrict__ dc) {
    int e = blockIdx.x * blockDim.x + threadIdx.x;
    if (e >= E) return;
    float v = ev[e];
    atomicAdd(&dr[er[e]], v);
    atomicAdd(&dc[ec[e]], v);
}

// ---------------- row histogram ----------------
__global__ void hist_kernel(const int* __restrict__ er, int E, int* __restrict__ cnt) {
    int e = blockIdx.x * blockDim.x + threadIdx.x;
    if (e >= E) return;
    atomicAdd(&cnt[er[e]], 1);
}

// ---------------- single-block exclusive scan: cnt[0..n-1] -> rptr[0..n] ----------------
__global__ void scan_kernel(const int* __restrict__ cnt, int* __restrict__ rptr, int n) {
    __shared__ int ssum[1024];
    int t = threadIdx.x;
    int chunk = (n + 1023) / 1024;
    int beg = t * chunk;
    int end = min(beg + chunk, n);
    int s = 0;
    for (int i = beg; i < end; i++) s += cnt[i];
    ssum[t] = s;
    __syncthreads();
    for (int off = 1; off < 1024; off <<= 1) {
        int v = (t >= off) ? ssum[t - off] : 0;
        __syncthreads();
        ssum[t] += v;
        __syncthreads();
    }
    int run = (t == 0) ? 0 : ssum[t - 1];
    for (int i = beg; i < end; i++) { rptr[i] = run; run += cnt[i]; }
    if (t == 0) rptr[n] = ssum[1023];
}

// ---------------- copy rptr -> cursor ----------------
__global__ void copy_kernel(const int* __restrict__ src, int* __restrict__ dst, int n) {
    int i = blockIdx.x * blockDim.x + threadIdx.x;
    if (i < n) dst[i] = src[i];
}

// ---------------- fill CSR: compute w, scatter (col, w) into row bucket ----------------
__global__ void fill_csr(const int* __restrict__ er, const int* __restrict__ ec,
                         const float* __restrict__ ev,
                         const float* __restrict__ dr, const float* __restrict__ dc,
                         int* __restrict__ cursor, int2* __restrict__ csr,
                         int E, int ebase) {
    int e = blockIdx.x * blockDim.x + threadIdx.x;
    if (e >= E) return;
    int r = er[e], c = ec[e];
    float w = ev[e] * rsqrtf(fmaxf(dr[r] * dc[c], 1e-12f));
    int pos = atomicAdd(&cursor[r], 1);
    int2 pk; pk.x = c; pk.y = __float_as_int(w);
    csr[ebase + pos] = pk;
}

// ---------------- init: gated GEMM + buffer init ----------------
// 4 nodes per block, 64 threads per node; thread computes one output column.
__global__ void init_kernel(const float* __restrict__ de, const float* __restrict__ se,
                            const float* __restrict__ Wr, const float* __restrict__ br,
                            const float* __restrict__ Wd, const float* __restrict__ bd,
                            float* __restrict__ G, float* __restrict__ cur,
                            float* __restrict__ eD, float* __restrict__ eS,
                            float* __restrict__ rds) {
    __shared__ float sW[64 * 64];
    __shared__ float sb[64];
    __shared__ float sx[4][64];
    bool isDis = (blockIdx.x >= (DRUGN / 4));
    const float* W = isDis ? Wd : Wr;
    const float* b = isDis ? bd : br;
    for (int t = threadIdx.x; t < 4096; t += blockDim.x) sW[t] = W[t];
    if (threadIdx.x < 64) sb[threadIdx.x] = b[threadIdx.x];

    int local = threadIdx.x >> 6;             // 0..3
    int j     = threadIdx.x & 63;             // output column
    int n = blockIdx.x * 4 + local;           // node 0..NRD-1
    const float* emb = isDis ? se : de;
    size_t lrow = isDis ? (size_t)(n - DRUGN) * 64 : (size_t)n * 64;
    sx[local][j] = emb[lrow + j];
    __syncthreads();

    float z = sb[j];
#pragma unroll 16
    for (int k = 0; k < 64; k++) z = fmaf(sx[local][k], sW[k * 64 + j], z);
    float x = sx[local][j];
    float g = x * (1.0f / (1.0f + expf(-z)));

    size_t base = (size_t)n * 64;
    G[base + j]   = g;
    cur[base + j] = x;
    rds[(size_t)n * 256 + j] = x;
    if (!isDis) eD[base + j] = g;
    else        eS[(size_t)(n - DRUGN) * 64 + j] = g;
}

// ---------------- SpMM (CSR gather): one warp per destination row ----------------
__global__ void spmm_csr(const int* __restrict__ rptr, const int2* __restrict__ csr,
                         const float* __restrict__ src, float* __restrict__ dst,
                         int nrows, int ebase, int coff, int roff) {
    int gw = (blockIdx.x * blockDim.x + threadIdx.x) >> 5;
    int lane = threadIdx.x & 31;
    if (gw >= nrows) return;
    int beg = rptr[gw], end = rptr[gw + 1];
    const int2* ep = csr + ebase;
    float a0 = 0.f, a1 = 0.f, b0 = 0.f, b1 = 0.f;
    int e = beg;
    for (; e + 1 < end; e += 2) {
        int2 p0 = ep[e], p1 = ep[e + 1];
        float w0 = __int_as_float(p0.y), w1 = __int_as_float(p1.y);
        const float* s0 = src + (size_t)(p0.x + coff) * 64;
        const float* s1 = src + (size_t)(p1.x + coff) * 64;
        a0 = fmaf(w0, s0[lane], a0);      a1 = fmaf(w0, s0[32 + lane], a1);
        b0 = fmaf(w1, s1[lane], b0);      b1 = fmaf(w1, s1[32 + lane], b1);
    }
    if (e < end) {
        int2 p = ep[e];
        float w = __int_as_float(p.y);
        const float* s = src + (size_t)(p.x + coff) * 64;
        a0 = fmaf(w, s[lane], a0);        a1 = fmaf(w, s[32 + lane], a1);
    }
    size_t d = (size_t)(gw + roff) * 64;
    dst[d + lane]      = a0 + b0;
    dst[d + 32 + lane] = a1 + b1;
}

// ---------------- per-layer combine: noise + norms + updates ----------------
// One warp handles drug row n and dis row n+DRUGN. Noise per element f:
// partitionable threefry, counter (0, f), bits = y0 ^ y1.
__global__ void combine_kernel(const float* __restrict__ P, const float* __restrict__ R,
                               float* __restrict__ cur, float* __restrict__ eD,
                               float* __restrict__ eS, float* __restrict__ rds,
                               int layer, uint32_t k0, uint32_t k1) {
    int gw = (blockIdx.x * blockDim.x + threadIdx.x) >> 5;
    int lane = threadIdx.x & 31;
    if (gw >= DRUGN) return;
    size_t bn = (size_t)gw * 64;
    size_t bm = (size_t)(gw + DRUGN) * 64;

    uint32_t f0 = (uint32_t)gw * 64u + (uint32_t)lane;
    float un0 = u01(tf_bits32(k0, k1, f0));                 // drug row, col lane
    float un1 = u01(tf_bits32(k0, k1, f0 + 32u));           // drug row, col lane+32
    float um0 = u01(tf_bits32(k0, k1, f0 + HBITS));         // dis row,  col lane
    float um1 = u01(tf_bits32(k0, k1, f0 + 32u + HBITS));   // dis row,  col lane+32

    float sn = fmaf(un0, un0, un1 * un1);
    float sm = fmaf(um0, um0, um1 * um1);
#pragma unroll
    for (int o = 16; o; o >>= 1) {
        sn += __shfl_xor_sync(0xffffffffu, sn, o);
        sm += __shfl_xor_sync(0xffffffffu, sm, o);
    }
    float scn = EPSF / fmaxf(sqrtf(sn), 1e-12f);
    float scm = EPSF / fmaxf(sqrtf(sm), 1e-12f);

    float rn0 = R[bn + lane], rn1 = R[bn + 32 + lane];
    float rm0 = R[bm + lane], rm1 = R[bm + 32 + lane];
    rn0 += fsgn(rn0) * un0 * scn;  rn1 += fsgn(rn1) * un1 * scn;
    rm0 += fsgn(rm0) * um0 * scm;  rm1 += fsgn(rm1) * um1 * scm;

    float qn = fmaf(rn0, rn0, rn1 * rn1);
    float qm = fmaf(rm0, rm0, rm1 * rm1);
#pragma unroll
    for (int o = 16; o; o >>= 1) {
        qn += __shfl_xor_sync(0xffffffffu, qn, o);
        qm += __shfl_xor_sync(0xffffffffu, qm, o);
    }
    float inr = 1.f / fmaxf(sqrtf(qn), 1e-12f);
    float imr = 1.f / fmaxf(sqrtf(qm), 1e-12f);

    size_t snb = (size_t)gw * 256 + (size_t)(layer + 1) * 64;
    size_t smb = (size_t)(gw + DRUGN) * 256 + (size_t)(layer + 1) * 64;
    rds[snb + lane] = rn0 * inr;  rds[snb + 32 + lane] = rn1 * inr;
    rds[smb + lane] = rm0 * imr;  rds[smb + 32 + lane] = rm1 * imr;

    float pn0 = P[bn + lane], pn1 = P[bn + 32 + lane];
    float pm0 = P[bm + lane], pm1 = P[bm + 32 + lane];
    cur[bn + lane]      = 0.5f * pn0 + 0.5f * rn0;
    cur[bn + 32 + lane] = 0.5f * pn1 + 0.5f * rn1;
    cur[bm + lane]      = 0.5f * pm0 + 0.5f * rm0;
    cur[bm + 32 + lane] = 0.5f * pm1 + 0.5f * rm1;

    float tn = fmaf(pn0, pn0, pn1 * pn1);
    float tm = fmaf(pm0, pm0, pm1 * pm1);
#pragma unroll
    for (int o = 16; o; o >>= 1) {
        tn += __shfl_xor_sync(0xffffffffu, tn, o);
        tm += __shfl_xor_sync(0xffffffffu, tm, o);
    }
    float ipn = 1.f / fmaxf(sqrtf(tn), 1e-12f);
    float ipm = 1.f / fmaxf(sqrtf(tm), 1e-12f);

    eD[bn + lane]      += pn0 * ipn;
    eD[bn + 32 + lane] += pn1 * ipn;
    size_t bs = (size_t)gw * 64;
    eS[bs + lane]      += pm0 * ipm;
    eS[bs + 32 + lane] += pm1 * ipm;
}

// ---------------- final: scale means, combine with embeddings ----------------
__global__ void final_kernel(const float* __restrict__ de, const float* __restrict__ se,
                             float* __restrict__ out) {
    size_t i = (size_t)blockIdx.x * blockDim.x + threadIdx.x;
    if (i == 0) out[OFF_LOSS] = 0.f;
    if (i < 6400000) {
        float E = out[OFF_DRUGE + i] * 0.25f;
        float emb = de[i];
        out[OFF_DRUGE + i] = E;
        out[OFF_DRUGALL + i] = 0.5f * emb + 0.5f * E;
        out[OFF_RDDRUG + i] = emb;
    } else if (i < 12800000) {
        size_t j = i - 6400000;
        float E = out[OFF_DISE + j] * 0.25f;
        float emb = se[j];
        out[OFF_DISE + j] = E;
        out[OFF_DISALL + j] = 0.5f * emb + 0.5f * E;
        out[OFF_RDDIS + j] = emb;
    }
}

// ---------------- host-side threefry for key folding ----------------
static inline void tf_host(uint32_t k0, uint32_t k1, uint32_t* px0, uint32_t* px1) {
    uint32_t x0 = *px0, x1 = *px1;
    uint32_t k2 = k0 ^ k1 ^ 0x1BD11BDAu;
#define HROT(r) { x0 += x1; x1 = (x1 << r) | (x1 >> (32 - r)); x1 ^= x0; }
    x0 += k0; x1 += k1;
    HROT(13) HROT(15) HROT(26) HROT(6)
    x0 += k1; x1 += k2 + 1u;
    HROT(17) HROT(29) HROT(16) HROT(24)
    x0 += k2; x1 += k0 + 2u;
    HROT(13) HROT(15) HROT(26) HROT(6)
    x0 += k0; x1 += k1 + 3u;
    HROT(17) HROT(29) HROT(16) HROT(24)
    x0 += k1; x1 += k2 + 4u;
    HROT(13) HROT(15) HROT(26) HROT(6)
    x0 += k2; x1 += k0 + 5u;
#undef HROT
    *px0 = x0; *px1 = x1;
}

extern "C" void kernel_launch(void* const* d_in, const int* in_sizes, int n_in,
                              void* d_out, int out_size) {
    const float* drug_emb = (const float*)d_in[0];
    const float* dis_emb  = (const float*)d_in[1];
    const float* Wr = (const float*)d_in[2];
    const float* br = (const float*)d_in[3];
    const float* Wd = (const float*)d_in[4];
    const float* bd = (const float*)d_in[5];
    const int*   rr_row = (const int*)d_in[6];
    const int*   rr_col = (const int*)d_in[7];
    const float* rr_val = (const float*)d_in[8];
    const int*   dd_row = (const int*)d_in[9];
    const int*   dd_col = (const int*)d_in[10];
    const float* dd_val = (const float*)d_in[11];
    const int*   rd_row = (const int*)d_in[12];
    const int*   rd_col = (const int*)d_in[13];
    const float* rd_val = (const float*)d_in[14];
    float* out = (float*)d_out;

    float *G, *cur, *P, *R, *deg;
    int2 *csr; int *cnt, *rptr, *cursor;
    cudaGetSymbolAddress((void**)&G,     g_G);
    cudaGetSymbolAddress((void**)&cur,   g_cur);
    cudaGetSymbolAddress((void**)&P,     g_P);
    cudaGetSymbolAddress((void**)&R,     g_R);
    cudaGetSymbolAddress((void**)&deg,   g_deg);
    cudaGetSymbolAddress((void**)&csr,   g_csr);
    cudaGetSymbolAddress((void**)&cnt,   g_cnt);
    cudaGetSymbolAddress((void**)&rptr,  g_rptr);
    cudaGetSymbolAddress((void**)&cursor,g_cursor);

    // ---- one-time per launch: degrees + CSR build (graph-invariant) ----
    cudaMemsetAsync(deg, 0, 800000 * sizeof(float), 0);
    cudaMemsetAsync(cnt, 0, 400000 * sizeof(int), 0);

    deg_kernel<<<(EDG_RR + 255) / 256, 256>>>(rr_row, rr_col, rr_val, EDG_RR, deg + DRR_R, deg + DRR_C);
    deg_kernel<<<(EDG_DD + 255) / 256, 256>>>(dd_row, dd_col, dd_val, EDG_DD, deg + DDD_R, deg + DDD_C);
    deg_kernel<<<(EDG_RD + 255) / 256, 256>>>(rd_row, rd_col, rd_val, EDG_RD, deg + DRD_R, deg + DRD_C);

    hist_kernel<<<(EDG_RR + 255) / 256, 256>>>(rr_row, EDG_RR, cnt + CNT_RR);
    hist_kernel<<<(EDG_DD + 255) / 256, 256>>>(dd_row, EDG_DD, cnt + CNT_DD);
    hist_kernel<<<(EDG_RD + 255) / 256, 256>>>(rd_row, EDG_RD, cnt + CNT_RD);

    scan_kernel<<<1, 1024>>>(cnt + CNT_RR, rptr + RP_RR, DRUGN);
    scan_kernel<<<1, 1024>>>(cnt + CNT_DD, rptr + RP_DD, DISN);
    scan_kernel<<<1, 1024>>>(cnt + CNT_RD, rptr + RP_RD, NRD);

    copy_kernel<<<(400003 + 255) / 256, 256>>>(rptr, cursor, 400003);

    fill_csr<<<(EDG_RR + 255) / 256, 256>>>(rr_row, rr_col, rr_val, deg + DRR_R, deg + DRR_C,
                                            cursor + RP_RR, csr, EDG_RR, EB_RR);
    fill_csr<<<(EDG_DD + 255) / 256, 256>>>(dd_row, dd_col, dd_val, deg + DDD_R, deg + DDD_C,
                                            cursor + RP_DD, csr, EDG_DD, EB_DD);
    fill_csr<<<(EDG_RD + 255) / 256, 256>>>(rd_row, rd_col, rd_val, deg + DRD_R, deg + DRD_C,
                                            cursor + RP_RD, csr, EDG_RD, EB_RD);

    // ---- init: gates, cur = raw emb, rd_stack slice 0, drugE/disE accumulators ----
    init_kernel<<<NRD / 4, 256>>>(drug_emb, dis_emb, Wr, br, Wd, bd,
                                  G, cur, out + OFF_DRUGE, out + OFF_DISE, out + OFF_RDSTACK);

    for (int i = 0; i < 3; i++) {
        // fold_in(key(1), i): threefry2x32(key=(0,1), count=(0,i))
        uint32_t lk0 = 0u, lk1 = (uint32_t)i;
        tf_host(0u, 1u, &lk0, &lk1);

        const float* srcG = (i == 0) ? G : cur;
        spmm_csr<<<(DRUGN * 32 + 255) / 256, 256>>>(rptr + RP_RR, csr, srcG, P,
                                                    DRUGN, EB_RR, 0, 0);
        spmm_csr<<<(DISN * 32 + 255) / 256, 256>>>(rptr + RP_DD, csr, srcG, P,
                                                   DISN, EB_DD, DRUGN, DRUGN);
        spmm_csr<<<(NRD * 32 + 255) / 256, 256>>>(rptr + RP_RD, csr, cur, R,
                                                  NRD, EB_RD, 0, 0);

        combine_kernel<<<(DRUGN * 32) / 256, 256>>>(P, R, cur,
            out + OFF_DRUGE, out + OFF_DISE, out + OFF_RDSTACK, i, lk0, lk1);
    }

    final_kernel<<<(12800000 + 255) / 256, 256>>>(drug_emb, dis_emb, out);
}

// round 8
// speedup vs baseline: 1.1835x; 1.0028x over previous
#include <cuda_runtime.h>
#include <stdint.h>
#include <stddef.h>

// Problem constants
#define DRUGN   100000
#define DISN    100000
#define NRD     200000
#define HIDN    64
#define EDG_RR  1600000
#define EDG_DD  1600000
#define EDG_RD  3200000
#define E_TOT   6400000
#define HBITS   6400000u     // flat-index offset of dis rows (100000*64)
#define EPSF    0.1f

// Output packing (float32), tuple order:
// drugE, disE, drugAll, disAll, rd_drug, rd_dis, meta_reg_loss, rd_stack
static const size_t OFF_DRUGE   = 0;
static const size_t OFF_DISE    = 6400000;
static const size_t OFF_DRUGALL = 12800000;
static const size_t OFF_DISALL  = 19200000;
static const size_t OFF_RDDRUG  = 25600000;
static const size_t OFF_RDDIS   = 32000000;
static const size_t OFF_LOSS    = 38400000;
static const size_t OFF_RDSTACK = 38400001;

// Scratch (static device arrays: no runtime allocation allowed)
__device__ float g_G   [(size_t)NRD * HIDN];  // gated init (rr0 | dd0)
__device__ float g_curA[(size_t)NRD * HIDN];  // cur ping
__device__ float g_curB[(size_t)NRD * HIDN];  // cur pong
__device__ float g_deg[800000];               // degree sums: 6 slices
__device__ int2  g_csr[E_TOT];                // packed (col, w) per edge, CSR order
__device__ int   g_cnt[400000];               // row counts: rr|dd|rd
__device__ int   g_rptr[400003];              // row pointers: rr|dd|rd (each +1)
__device__ int   g_cursor[400003];            // scatter cursors (copy of rptr)

// deg slices
#define DRR_R 0
#define DRR_C 100000
#define DDD_R 200000
#define DDD_C 300000
#define DRD_R 400000
#define DRD_C 600000
// count slices
#define CNT_RR 0
#define CNT_DD 100000
#define CNT_RD 200000
// rowptr slices
#define RP_RR 0
#define RP_DD 100001
#define RP_RD 200002
// edge-base slices in g_csr
#define EB_RR 0
#define EB_DD 1600000
#define EB_RD 3200000

// ---------------- threefry2x32 (bit-exact JAX core) ----------------
#define TFROUND(x0,x1,r) { x0 += x1; x1 = __funnelshift_l(x1,x1,r); x1 ^= x0; }

__device__ __forceinline__ void tf2x32(uint32_t k0, uint32_t k1, uint32_t &x0, uint32_t &x1) {
    uint32_t k2 = k0 ^ k1 ^ 0x1BD11BDAu;
    x0 += k0; x1 += k1;
    TFROUND(x0,x1,13) TFROUND(x0,x1,15) TFROUND(x0,x1,26) TFROUND(x0,x1,6)
    x0 += k1; x1 += k2 + 1u;
    TFROUND(x0,x1,17) TFROUND(x0,x1,29) TFROUND(x0,x1,16) TFROUND(x0,x1,24)
    x0 += k2; x1 += k0 + 2u;
    TFROUND(x0,x1,13) TFROUND(x0,x1,15) TFROUND(x0,x1,26) TFROUND(x0,x1,6)
    x0 += k0; x1 += k1 + 3u;
    TFROUND(x0,x1,17) TFROUND(x0,x1,29) TFROUND(x0,x1,16) TFROUND(x0,x1,24)
    x0 += k1; x1 += k2 + 4u;
    TFROUND(x0,x1,13) TFROUND(x0,x1,15) TFROUND(x0,x1,26) TFROUND(x0,x1,6)
    x0 += k2; x1 += k0 + 5u;
}

// Partitionable-threefry random bits: counter (0, f); bits = y0 ^ y1.
__device__ __forceinline__ uint32_t tf_bits32(uint32_t k0, uint32_t k1, uint32_t f) {
    uint32_t x0 = 0u, x1 = f;
    tf2x32(k0, k1, x0, x1);
    return x0 ^ x1;
}

__device__ __forceinline__ float u01(uint32_t b) {
    return __uint_as_float((b >> 9) | 0x3f800000u) - 1.0f;
}
__device__ __forceinline__ float fsgn(float x) {
    return (x > 0.f) ? 1.f : ((x < 0.f) ? -1.f : 0.f);
}

// ---------------- fused degree + row-histogram (one edge pass) ----------------
__global__ void deghist_kernel(const int* __restrict__ er, const int* __restrict__ ec,
                               const float* __restrict__ ev, int E,
                               float* __restrict__ dr, float* __restrict__ dc,
                               int* __restrict__ cnt) {
    int e = blockIdx.x * blockDim.x + threadIdx.x;
    if (e >= E) return;
    int r = er[e];
    float v = ev[e];
    atomicAdd(&dr[r], v);
    atomicAdd(&dc[ec[e]], v);
    atomicAdd(&cnt[r], 1);
}

// ---------------- single-block exclusive scan: cnt[0..n-1] -> rptr[0..n] ----------------
__global__ void scan_kernel(const int* __restrict__ cnt, int* __restrict__ rptr, int n) {
    __shared__ int ssum[1024];
    int t = threadIdx.x;
    int chunk = (n + 1023) / 1024;
    int beg = t * chunk;
    int end = min(beg + chunk, n);
    int s = 0;
    for (int i = beg; i < end; i++) s += cnt[i];
    ssum[t] = s;
    __syncthreads();
    for (int off = 1; off < 1024; off <<= 1) {
        int v = (t >= off) ? ssum[t - off] : 0;
        __syncthreads();
        ssum[t] += v;
        __syncthreads();
    }
    int run = (t == 0) ? 0 : ssum[t - 1];
    for (int i = beg; i < end; i++) { rptr[i] = run; run += cnt[i]; }
    if (t == 0) rptr[n] = ssum[1023];
}

// ---------------- copy rptr -> cursor ----------------
__global__ void copy_kernel(const int* __restrict__ src, int* __restrict__ dst, int n) {
    int i = blockIdx.x * blockDim.x + threadIdx.x;
    if (i < n) dst[i] = src[i];
}

// ---------------- fill CSR: compute w, scatter (col, w) into row bucket ----------------
__global__ void fill_csr(const int* __restrict__ er, const int* __restrict__ ec,
                         const float* __restrict__ ev,
                         const float* __restrict__ dr, const float* __restrict__ dc,
                         int* __restrict__ cursor, int2* __restrict__ csr,
                         int E, int ebase) {
    int e = blockIdx.x * blockDim.x + threadIdx.x;
    if (e >= E) return;
    int r = er[e], c = ec[e];
    float w = ev[e] * rsqrtf(fmaxf(dr[r] * dc[c], 1e-12f));
    int pos = atomicAdd(&cursor[r], 1);
    int2 pk; pk.x = c; pk.y = __float_as_int(w);
    csr[ebase + pos] = pk;
}

// ---------------- init: gated GEMM + buffer init ----------------
__global__ void init_kernel(const float* __restrict__ de, const float* __restrict__ se,
                            const float* __restrict__ Wr, const float* __restrict__ br,
                            const float* __restrict__ Wd, const float* __restrict__ bd,
                            float* __restrict__ G, float* __restrict__ cur,
                            float* __restrict__ eD, float* __restrict__ eS,
                            float* __restrict__ rds) {
    __shared__ float sW[64 * 64];
    __shared__ float sb[64];
    __shared__ float sx[4][64];
    bool isDis = (blockIdx.x >= (DRUGN / 4));
    const float* W = isDis ? Wd : Wr;
    const float* b = isDis ? bd : br;
    for (int t = threadIdx.x; t < 4096; t += blockDim.x) sW[t] = W[t];
    if (threadIdx.x < 64) sb[threadIdx.x] = b[threadIdx.x];

    int local = threadIdx.x >> 6;             // 0..3
    int j     = threadIdx.x & 63;             // output column
    int n = blockIdx.x * 4 + local;           // node 0..NRD-1
    const float* emb = isDis ? se : de;
    size_t lrow = isDis ? (size_t)(n - DRUGN) * 64 : (size_t)n * 64;
    sx[local][j] = emb[lrow + j];
    __syncthreads();

    float z = sb[j];
#pragma unroll 16
    for (int k = 0; k < 64; k++) z = fmaf(sx[local][k], sW[k * 64 + j], z);
    float x = sx[local][j];
    float g = x * (1.0f / (1.0f + expf(-z)));

    size_t base = (size_t)n * 64;
    G[base + j]   = g;
    cur[base + j] = x;
    rds[(size_t)n * 256 + j] = x;
    if (!isDis) eD[base + j] = g;
    else        eS[(size_t)(n - DRUGN) * 64 + j] = g;
}

// ---------------- CSR row gather into registers (2-way unrolled) ----------------
__device__ __forceinline__ void accum_row(const int2* __restrict__ ep, int beg, int end,
                                          const float* __restrict__ src, int coff, int lane,
                                          float &o0, float &o1) {
    float a0 = 0.f, a1 = 0.f, b0 = 0.f, b1 = 0.f;
    int e = beg;
    for (; e + 1 < end; e += 2) {
        int2 p0 = ep[e], p1 = ep[e + 1];
        float w0 = __int_as_float(p0.y), w1 = __int_as_float(p1.y);
        const float* s0 = src + (size_t)(p0.x + coff) * 64;
        const float* s1 = src + (size_t)(p1.x + coff) * 64;
        a0 = fmaf(w0, s0[lane], a0);      a1 = fmaf(w0, s0[32 + lane], a1);
        b0 = fmaf(w1, s1[lane], b0);      b1 = fmaf(w1, s1[32 + lane], b1);
    }
    if (e < end) {
        int2 p = ep[e];
        float w = __int_as_float(p.y);
        const float* s = src + (size_t)(p.x + coff) * 64;
        a0 = fmaf(w, s[lane], a0);        a1 = fmaf(w, s[32 + lane], a1);
    }
    o0 = a0 + b0; o1 = a1 + b1;
}

// ---------------- fused per-layer kernel ----------------
// One warp handles drug row n and dis row m=n+DRUGN: computes the 4 propagated
// rows (rr->P[n], dd->P[m], rd->R[n], rd->R[m]) in registers, then does noise,
// norms, cur update, rd_stack slice, and drugE/disE accumulation inline.
__global__ void layer_kernel(const int* __restrict__ rptr, const int2* __restrict__ csr,
                             const float* __restrict__ srcPD,  // G (layer0) or curA
                             const float* __restrict__ srcR,   // curA
                             float* __restrict__ curB,         // next cur (unused layer 2)
                             float* __restrict__ eD, float* __restrict__ eS,
                             float* __restrict__ rds,
                             int layer, uint32_t k0, uint32_t k1) {
    int gw = (blockIdx.x * blockDim.x + threadIdx.x) >> 5;
    int lane = threadIdx.x & 31;
    if (gw >= DRUGN) return;
    int m = gw + DRUGN;

    // ---- four gathered rows ----
    float pn0, pn1, pm0, pm1, rn0, rn1, rm0, rm1;
    accum_row(csr + EB_RR, rptr[RP_RR + gw], rptr[RP_RR + gw + 1], srcPD, 0,     lane, pn0, pn1);
    accum_row(csr + EB_DD, rptr[RP_DD + gw], rptr[RP_DD + gw + 1], srcPD, DRUGN, lane, pm0, pm1);
    accum_row(csr + EB_RD, rptr[RP_RD + gw], rptr[RP_RD + gw + 1], srcR,  0,     lane, rn0, rn1);
    accum_row(csr + EB_RD, rptr[RP_RD + m],  rptr[RP_RD + m + 1],  srcR,  0,     lane, rm0, rm1);

    // ---- noise (partitionable threefry) ----
    uint32_t f0 = (uint32_t)gw * 64u + (uint32_t)lane;
    float un0 = u01(tf_bits32(k0, k1, f0));
    float un1 = u01(tf_bits32(k0, k1, f0 + 32u));
    float um0 = u01(tf_bits32(k0, k1, f0 + HBITS));
    float um1 = u01(tf_bits32(k0, k1, f0 + 32u + HBITS));

    float sn = fmaf(un0, un0, un1 * un1);
    float sm = fmaf(um0, um0, um1 * um1);
#pragma unroll
    for (int o = 16; o; o >>= 1) {
        sn += __shfl_xor_sync(0xffffffffu, sn, o);
        sm += __shfl_xor_sync(0xffffffffu, sm, o);
    }
    float scn = EPSF / fmaxf(sqrtf(sn), 1e-12f);
    float scm = EPSF / fmaxf(sqrtf(sm), 1e-12f);

    rn0 += fsgn(rn0) * un0 * scn;  rn1 += fsgn(rn1) * un1 * scn;
    rm0 += fsgn(rm0) * um0 * scm;  rm1 += fsgn(rm1) * um1 * scm;

    // ---- l2n(r0) -> rd_stack slice layer+1 ----
    float qn = fmaf(rn0, rn0, rn1 * rn1);
    float qm = fmaf(rm0, rm0, rm1 * rm1);
#pragma unroll
    for (int o = 16; o; o >>= 1) {
        qn += __shfl_xor_sync(0xffffffffu, qn, o);
        qm += __shfl_xor_sync(0xffffffffu, qm, o);
    }
    float inr = 1.f / fmaxf(sqrtf(qn), 1e-12f);
    float imr = 1.f / fmaxf(sqrtf(qm), 1e-12f);

    size_t snb = (size_t)gw * 256 + (size_t)(layer + 1) * 64;
    size_t smb = (size_t)m * 256 + (size_t)(layer + 1) * 64;
    rds[snb + lane] = rn0 * inr;  rds[snb + 32 + lane] = rn1 * inr;
    rds[smb + lane] = rm0 * imr;  rds[smb + 32 + lane] = rm1 * imr;

    // ---- cur update (skip on last layer: never read again) ----
    size_t bn = (size_t)gw * 64;
    size_t bm = (size_t)m * 64;
    if (layer < 2) {
        curB[bn + lane]      = 0.5f * pn0 + 0.5f * rn0;
        curB[bn + 32 + lane] = 0.5f * pn1 + 0.5f * rn1;
        curB[bm + lane]      = 0.5f * pm0 + 0.5f * rm0;
        curB[bm + 32 + lane] = 0.5f * pm1 + 0.5f * rm1;
    }

    // ---- l2n(d0)/l2n(s0) accumulated into drugE/disE ----
    float tn = fmaf(pn0, pn0, pn1 * pn1);
    float tm = fmaf(pm0, pm0, pm1 * pm1);
#pragma unroll
    for (int o = 16; o; o >>= 1) {
        tn += __shfl_xor_sync(0xffffffffu, tn, o);
        tm += __shfl_xor_sync(0xffffffffu, tm, o);
    }
    float ipn = 1.f / fmaxf(sqrtf(tn), 1e-12f);
    float ipm = 1.f / fmaxf(sqrtf(tm), 1e-12f);

    eD[bn + lane]      += pn0 * ipn;
    eD[bn + 32 + lane] += pn1 * ipn;
    eS[bn + lane]      += pm0 * ipm;
    eS[bn + 32 + lane] += pm1 * ipm;
}

// ---------------- final: scale means, combine with embeddings ----------------
__global__ void final_kernel(const float* __restrict__ de, const float* __restrict__ se,
                             float* __restrict__ out) {
    size_t i = (size_t)blockIdx.x * blockDim.x + threadIdx.x;
    if (i == 0) out[OFF_LOSS] = 0.f;
    if (i < 6400000) {
        float E = out[OFF_DRUGE + i] * 0.25f;
        float emb = de[i];
        out[OFF_DRUGE + i] = E;
        out[OFF_DRUGALL + i] = 0.5f * emb + 0.5f * E;
        out[OFF_RDDRUG + i] = emb;
    } else if (i < 12800000) {
        size_t j = i - 6400000;
        float E = out[OFF_DISE + j] * 0.25f;
        float emb = se[j];
        out[OFF_DISE + j] = E;
        out[OFF_DISALL + j] = 0.5f * emb + 0.5f * E;
        out[OFF_RDDIS + j] = emb;
    }
}

// ---------------- host-side threefry for key folding ----------------
static inline void tf_host(uint32_t k0, uint32_t k1, uint32_t* px0, uint32_t* px1) {
    uint32_t x0 = *px0, x1 = *px1;
    uint32_t k2 = k0 ^ k1 ^ 0x1BD11BDAu;
#define HROT(r) { x0 += x1; x1 = (x1 << r) | (x1 >> (32 - r)); x1 ^= x0; }
    x0 += k0; x1 += k1;
    HROT(13) HROT(15) HROT(26) HROT(6)
    x0 += k1; x1 += k2 + 1u;
    HROT(17) HROT(29) HROT(16) HROT(24)
    x0 += k2; x1 += k0 + 2u;
    HROT(13) HROT(15) HROT(26) HROT(6)
    x0 += k0; x1 += k1 + 3u;
    HROT(17) HROT(29) HROT(16) HROT(24)
    x0 += k1; x1 += k2 + 4u;
    HROT(13) HROT(15) HROT(26) HROT(6)
    x0 += k2; x1 += k0 + 5u;
#undef HROT
    *px0 = x0; *px1 = x1;
}

extern "C" void kernel_launch(void* const* d_in, const int* in_sizes, int n_in,
                              void* d_out, int out_size) {
    const float* drug_emb = (const float*)d_in[0];
    const float* dis_emb  = (const float*)d_in[1];
    const float* Wr = (const float*)d_in[2];
    const float* br = (const float*)d_in[3];
    const float* Wd = (const float*)d_in[4];
    const float* bd = (const float*)d_in[5];
    const int*   rr_row = (const int*)d_in[6];
    const int*   rr_col = (const int*)d_in[7];
    const float* rr_val = (const float*)d_in[8];
    const int*   dd_row = (const int*)d_in[9];
    const int*   dd_col = (const int*)d_in[10];
    const float* dd_val = (const float*)d_in[11];
    const int*   rd_row = (const int*)d_in[12];
    const int*   rd_col = (const int*)d_in[13];
    const float* rd_val = (const float*)d_in[14];
    float* out = (float*)d_out;

    float *G, *curA, *curB, *deg;
    int2 *csr; int *cnt, *rptr, *cursor;
    cudaGetSymbolAddress((void**)&G,     g_G);
    cudaGetSymbolAddress((void**)&curA,  g_curA);
    cudaGetSymbolAddress((void**)&curB,  g_curB);
    cudaGetSymbolAddress((void**)&deg,   g_deg);
    cudaGetSymbolAddress((void**)&csr,   g_csr);
    cudaGetSymbolAddress((void**)&cnt,   g_cnt);
    cudaGetSymbolAddress((void**)&rptr,  g_rptr);
    cudaGetSymbolAddress((void**)&cursor,g_cursor);

    // ---- one-time per launch: degrees + CSR build (graph-invariant) ----
    cudaMemsetAsync(deg, 0, 800000 * sizeof(float), 0);
    cudaMemsetAsync(cnt, 0, 400000 * sizeof(int), 0);

    deghist_kernel<<<(EDG_RR + 255) / 256, 256>>>(rr_row, rr_col, rr_val, EDG_RR,
                                                  deg + DRR_R, deg + DRR_C, cnt + CNT_RR);
    deghist_kernel<<<(EDG_DD + 255) / 256, 256>>>(dd_row, dd_col, dd_val, EDG_DD,
                                                  deg + DDD_R, deg + DDD_C, cnt + CNT_DD);
    deghist_kernel<<<(EDG_RD + 255) / 256, 256>>>(rd_row, rd_col, rd_val, EDG_RD,
                                                  deg + DRD_R, deg + DRD_C, cnt + CNT_RD);

    scan_kernel<<<1, 1024>>>(cnt + CNT_RR, rptr + RP_RR, DRUGN);
    scan_kernel<<<1, 1024>>>(cnt + CNT_DD, rptr + RP_DD, DISN);
    scan_kernel<<<1, 1024>>>(cnt + CNT_RD, rptr + RP_RD, NRD);

    copy_kernel<<<(400003 + 255) / 256, 256>>>(rptr, cursor, 400003);

    fill_csr<<<(EDG_RR + 255) / 256, 256>>>(rr_row, rr_col, rr_val, deg + DRR_R, deg + DRR_C,
                                            cursor + RP_RR, csr, EDG_RR, EB_RR);
    fill_csr<<<(EDG_DD + 255) / 256, 256>>>(dd_row, dd_col, dd_val, deg + DDD_R, deg + DDD_C,
                                            cursor + RP_DD, csr, EDG_DD, EB_DD);
    fill_csr<<<(EDG_RD + 255) / 256, 256>>>(rd_row, rd_col, rd_val, deg + DRD_R, deg + DRD_C,
                                            cursor + RP_RD, csr, EDG_RD, EB_RD);

    // ---- init: gates, curA = raw emb, rd_stack slice 0, drugE/disE accumulators ----
    init_kernel<<<NRD / 4, 256>>>(drug_emb, dis_emb, Wr, br, Wd, bd,
                                  G, curA, out + OFF_DRUGE, out + OFF_DISE, out + OFF_RDSTACK);

    // ---- fused layers ----
    float* bufs[2] = { curA, curB };
    for (int i = 0; i < 3; i++) {
        uint32_t lk0 = 0u, lk1 = (uint32_t)i;
        tf_host(0u, 1u, &lk0, &lk1);           // fold_in(key(1), i)
        const float* ca = bufs[i & 1];
        float*       cb = bufs[(i + 1) & 1];
        const float* srcPD = (i == 0) ? G : ca;
        layer_kernel<<<(DRUGN * 32 + 255) / 256, 256>>>(rptr, csr, srcPD, ca, cb,
            out + OFF_DRUGE, out + OFF_DISE, out + OFF_RDSTACK, i, lk0, lk1);
    }

    final_kernel<<<(12800000 + 255) / 256, 256>>>(drug_emb, dis_emb, out);
}

// round 10
// speedup vs baseline: 1.4273x; 1.2060x over previous
#include <cuda_runtime.h>
#include <stdint.h>
#include <stddef.h>

// Problem constants
#define DRUGN   100000
#define DISN    100000
#define NRD     200000
#define HIDN    64
#define EDG_RR  1600000
#define EDG_DD  1600000
#define EDG_RD  3200000
#define E_TOT   6400000
#define HBITS   6400000u     // flat-index offset of dis rows (100000*64)
#define EPSF    0.1f

// Output packing (float32), tuple order:
// drugE, disE, drugAll, disAll, rd_drug, rd_dis, meta_reg_loss, rd_stack
static const size_t OFF_DRUGE   = 0;
static const size_t OFF_DISE    = 6400000;
static const size_t OFF_DRUGALL = 12800000;
static const size_t OFF_DISALL  = 19200000;
static const size_t OFF_RDDRUG  = 25600000;
static const size_t OFF_RDDIS   = 32000000;
static const size_t OFF_LOSS    = 38400000;
static const size_t OFF_RDSTACK = 38400001;

// Scratch (static device arrays: no runtime allocation allowed)
__device__ float g_G   [(size_t)NRD * HIDN];  // gated init (rr0 | dd0)
__device__ float g_curA[(size_t)NRD * HIDN];  // cur ping
__device__ float g_curB[(size_t)NRD * HIDN];  // cur pong
__device__ float g_deg[800000];               // degree sums: 6 slices
__device__ int2  g_csr[E_TOT];                // packed (col, w) per edge, global CSR order
__device__ int   g_cnt[400000];               // row counts: rr|dd|rd (contiguous)
__device__ int   g_rptr[400001];              // GLOBAL row pointers (exclusive scan of cnt)
__device__ int   g_cursor[400001];            // scatter cursors (copy of rptr)
__device__ int   g_bsum[256];                 // per-block sums for multi-block scan
__device__ int   g_bscan[256];                // scanned block sums

// count/rptr slices (global scan makes edge offsets global automatically:
// prefix at 100000 == EDG_RR, at 200000 == EDG_RR+EDG_DD)
#define CNT_RR 0
#define CNT_DD 100000
#define CNT_RD 200000
// deg slices
#define DRR_R 0
#define DRR_C 100000
#define DDD_R 200000
#define DDD_C 300000
#define DRD_R 400000
#define DRD_C 600000

#define SCAN_N    400000
#define SCAN_BLK  2048
#define SCAN_NB   ((SCAN_N + SCAN_BLK - 1) / SCAN_BLK)   // 196

// ---------------- threefry2x32 (bit-exact JAX core) ----------------
#define TFROUND(x0,x1,r) { x0 += x1; x1 = __funnelshift_l(x1,x1,r); x1 ^= x0; }

__device__ __forceinline__ void tf2x32(uint32_t k0, uint32_t k1, uint32_t &x0, uint32_t &x1) {
    uint32_t k2 = k0 ^ k1 ^ 0x1BD11BDAu;
    x0 += k0; x1 += k1;
    TFROUND(x0,x1,13) TFROUND(x0,x1,15) TFROUND(x0,x1,26) TFROUND(x0,x1,6)
    x0 += k1; x1 += k2 + 1u;
    TFROUND(x0,x1,17) TFROUND(x0,x1,29) TFROUND(x0,x1,16) TFROUND(x0,x1,24)
    x0 += k2; x1 += k0 + 2u;
    TFROUND(x0,x1,13) TFROUND(x0,x1,15) TFROUND(x0,x1,26) TFROUND(x0,x1,6)
    x0 += k0; x1 += k1 + 3u;
    TFROUND(x0,x1,17) TFROUND(x0,x1,29) TFROUND(x0,x1,16) TFROUND(x0,x1,24)
    x0 += k1; x1 += k2 + 4u;
    TFROUND(x0,x1,13) TFROUND(x0,x1,15) TFROUND(x0,x1,26) TFROUND(x0,x1,6)
    x0 += k2; x1 += k0 + 5u;
}

// Partitionable-threefry random bits: counter (0, f); bits = y0 ^ y1.
__device__ __forceinline__ uint32_t tf_bits32(uint32_t k0, uint32_t k1, uint32_t f) {
    uint32_t x0 = 0u, x1 = f;
    tf2x32(k0, k1, x0, x1);
    return x0 ^ x1;
}

__device__ __forceinline__ float u01(uint32_t b) {
    return __uint_as_float((b >> 9) | 0x3f800000u) - 1.0f;
}
__device__ __forceinline__ float fsgn(float x) {
    return (x > 0.f) ? 1.f : ((x < 0.f) ? -1.f : 0.f);
}

// ---------------- fused degree + row-histogram (one edge pass) ----------------
__global__ void deghist_kernel(const int* __restrict__ er, const int* __restrict__ ec,
                               const float* __restrict__ ev, int E,
                               float* __restrict__ dr, float* __restrict__ dc,
                               int* __restrict__ cnt) {
    int e = blockIdx.x * blockDim.x + threadIdx.x;
    if (e >= E) return;
    int r = er[e];
    float v = ev[e];
    atomicAdd(&dr[r], v);
    atomicAdd(&dc[ec[e]], v);
    atomicAdd(&cnt[r], 1);
}

// ---------------- multi-block exclusive scan, stage 1 ----------------
// Each block scans SCAN_BLK elements (2 per thread) into rptr (local-exclusive),
// and writes its total into bsum[block].
__global__ void scan1_kernel(const int* __restrict__ cnt, int* __restrict__ rptr,
                             int* __restrict__ bsum) {
    __shared__ int ts[1024];
    int t = threadIdx.x;
    int base = blockIdx.x * SCAN_BLK;
    int i0 = base + 2 * t, i1 = i0 + 1;
    int v0 = (i0 < SCAN_N) ? cnt[i0] : 0;
    int v1 = (i1 < SCAN_N) ? cnt[i1] : 0;
    ts[t] = v0 + v1;
    __syncthreads();
    // Hillis-Steele inclusive scan over 1024 thread sums
    for (int off = 1; off < 1024; off <<= 1) {
        int v = (t >= off) ? ts[t - off] : 0;
        __syncthreads();
        ts[t] += v;
        __syncthreads();
    }
    int excl = (t == 0) ? 0 : ts[t - 1];
    if (i0 < SCAN_N) rptr[i0] = excl;
    if (i1 < SCAN_N) rptr[i1] = excl + v0;
    if (t == 1023) bsum[blockIdx.x] = ts[1023];
}

// ---------------- stage 2: scan the block sums (1 small block) ----------------
__global__ void scan2_kernel(const int* __restrict__ bsum, int* __restrict__ bscan) {
    __shared__ int ts[SCAN_NB];
    int t = threadIdx.x;
    if (t < SCAN_NB) ts[t] = bsum[t];
    __syncthreads();
    for (int off = 1; off < SCAN_NB; off <<= 1) {
        int v = (t >= off && t < SCAN_NB) ? ts[t - off] : 0;
        __syncthreads();
        if (t < SCAN_NB) ts[t] += v;
        __syncthreads();
    }
    if (t < SCAN_NB) bscan[t] = (t == 0) ? 0 : ts[t - 1];
}

// ---------------- stage 3: add block offsets; write rptr + cursor ----------------
__global__ void scan3_kernel(int* __restrict__ rptr, int* __restrict__ cursor,
                             const int* __restrict__ bscan) {
    int i = blockIdx.x * blockDim.x + threadIdx.x;
    if (i < SCAN_N) {
        int v = rptr[i] + bscan[i / SCAN_BLK];
        rptr[i] = v;
        cursor[i] = v;
    } else if (i == SCAN_N) {
        rptr[i] = E_TOT;
        cursor[i] = E_TOT;
    }
}

// ---------------- fill CSR: compute w, scatter (col, w) globally ----------------
__global__ void fill_csr(const int* __restrict__ er, const int* __restrict__ ec,
                         const float* __restrict__ ev,
                         const float* __restrict__ dr, const float* __restrict__ dc,
                         int* __restrict__ cursor, int2* __restrict__ csr, int E) {
    int e = blockIdx.x * blockDim.x + threadIdx.x;
    if (e >= E) return;
    int r = er[e], c = ec[e];
    float w = ev[e] * rsqrtf(fmaxf(dr[r] * dc[c], 1e-12f));
    int pos = atomicAdd(&cursor[r], 1);
    int2 pk; pk.x = c; pk.y = __float_as_int(w);
    csr[pos] = pk;
}

// ---------------- init: gated GEMM + buffer init ----------------
__global__ void init_kernel(const float* __restrict__ de, const float* __restrict__ se,
                            const float* __restrict__ Wr, const float* __restrict__ br,
                            const float* __restrict__ Wd, const float* __restrict__ bd,
                            float* __restrict__ G, float* __restrict__ cur,
                            float* __restrict__ eD, float* __restrict__ eS,
                            float* __restrict__ rds) {
    __shared__ float sW[64 * 64];
    __shared__ float sb[64];
    __shared__ float sx[4][64];
    bool isDis = (blockIdx.x >= (DRUGN / 4));
    const float* W = isDis ? Wd : Wr;
    const float* b = isDis ? bd : br;
    for (int t = threadIdx.x; t < 4096; t += blockDim.x) sW[t] = W[t];
    if (threadIdx.x < 64) sb[threadIdx.x] = b[threadIdx.x];

    int local = threadIdx.x >> 6;             // 0..3
    int j     = threadIdx.x & 63;             // output column
    int n = blockIdx.x * 4 + local;           // node 0..NRD-1
    const float* emb = isDis ? se : de;
    size_t lrow = isDis ? (size_t)(n - DRUGN) * 64 : (size_t)n * 64;
    sx[local][j] = emb[lrow + j];
    __syncthreads();

    float z = sb[j];
#pragma unroll 16
    for (int k = 0; k < 64; k++) z = fmaf(sx[local][k], sW[k * 64 + j], z);
    float x = sx[local][j];
    float g = x * (1.0f / (1.0f + expf(-z)));

    size_t base = (size_t)n * 64;
    G[base + j]   = g;
    cur[base + j] = x;
    rds[(size_t)n * 256 + j] = x;
    if (!isDis) eD[base + j] = g;
    else        eS[(size_t)(n - DRUGN) * 64 + j] = g;
}

// ---------------- CSR row gather into registers (4-way unrolled) ----------------
__device__ __forceinline__ void accum_row(const int2* __restrict__ ep, int beg, int end,
                                          const float* __restrict__ src, int coff, int lane,
                                          float &o0, float &o1) {
    float a0 = 0.f, a1 = 0.f, b0 = 0.f, b1 = 0.f;
    int e = beg;
    for (; e + 3 < end; e += 4) {
        int2 p0 = ep[e], p1 = ep[e + 1], p2 = ep[e + 2], p3 = ep[e + 3];
        const float* s0 = src + (size_t)(p0.x + coff) * 64;
        const float* s1 = src + (size_t)(p1.x + coff) * 64;
        const float* s2 = src + (size_t)(p2.x + coff) * 64;
        const float* s3 = src + (size_t)(p3.x + coff) * 64;
        float w0 = __int_as_float(p0.y), w1 = __int_as_float(p1.y);
        float w2 = __int_as_float(p2.y), w3 = __int_as_float(p3.y);
        a0 = fmaf(w0, s0[lane], a0);      a1 = fmaf(w0, s0[32 + lane], a1);
        b0 = fmaf(w1, s1[lane], b0);      b1 = fmaf(w1, s1[32 + lane], b1);
        a0 = fmaf(w2, s2[lane], a0);      a1 = fmaf(w2, s2[32 + lane], a1);
        b0 = fmaf(w3, s3[lane], b0);      b1 = fmaf(w3, s3[32 + lane], b1);
    }
    for (; e < end; e++) {
        int2 p = ep[e];
        float w = __int_as_float(p.y);
        const float* s = src + (size_t)(p.x + coff) * 64;
        a0 = fmaf(w, s[lane], a0);        a1 = fmaf(w, s[32 + lane], a1);
    }
    o0 = a0 + b0; o1 = a1 + b1;
}

// ---------------- fused per-layer kernel ----------------
// One warp handles drug row n and dis row m=n+DRUGN: computes the 4 propagated
// rows in registers, then noise, norms, cur update, rd_stack, drugE/disE.
__global__ void layer_kernel(const int* __restrict__ rptr, const int2* __restrict__ csr,
                             const float* __restrict__ srcPD,  // G (layer0) or curA
                             const float* __restrict__ srcR,   // curA
                             float* __restrict__ curB,         // next cur (unused layer 2)
                             float* __restrict__ eD, float* __restrict__ eS,
                             float* __restrict__ rds,
                             int layer, uint32_t k0, uint32_t k1) {
    int gw = (blockIdx.x * blockDim.x + threadIdx.x) >> 5;
    int lane = threadIdx.x & 31;
    if (gw >= DRUGN) return;
    int m = gw + DRUGN;

    // ---- four gathered rows (global CSR offsets) ----
    float pn0, pn1, pm0, pm1, rn0, rn1, rm0, rm1;
    accum_row(csr, rptr[CNT_RR + gw], rptr[CNT_RR + gw + 1], srcPD, 0,     lane, pn0, pn1);
    accum_row(csr, rptr[CNT_DD + gw], rptr[CNT_DD + gw + 1], srcPD, DRUGN, lane, pm0, pm1);
    accum_row(csr, rptr[CNT_RD + gw], rptr[CNT_RD + gw + 1], srcR,  0,     lane, rn0, rn1);
    accum_row(csr, rptr[CNT_RD + m],  rptr[CNT_RD + m + 1],  srcR,  0,     lane, rm0, rm1);

    // ---- noise (partitionable threefry) ----
    uint32_t f0 = (uint32_t)gw * 64u + (uint32_t)lane;
    float un0 = u01(tf_bits32(k0, k1, f0));
    float un1 = u01(tf_bits32(k0, k1, f0 + 32u));
    float um0 = u01(tf_bits32(k0, k1, f0 + HBITS));
    float um1 = u01(tf_bits32(k0, k1, f0 + 32u + HBITS));

    float sn = fmaf(un0, un0, un1 * un1);
    float sm = fmaf(um0, um0, um1 * um1);
#pragma unroll
    for (int o = 16; o; o >>= 1) {
        sn += __shfl_xor_sync(0xffffffffu, sn, o);
        sm += __shfl_xor_sync(0xffffffffu, sm, o);
    }
    float scn = EPSF / fmaxf(sqrtf(sn), 1e-12f);
    float scm = EPSF / fmaxf(sqrtf(sm), 1e-12f);

    rn0 += fsgn(rn0) * un0 * scn;  rn1 += fsgn(rn1) * un1 * scn;
    rm0 += fsgn(rm0) * um0 * scm;  rm1 += fsgn(rm1) * um1 * scm;

    // ---- l2n(r0) -> rd_stack slice layer+1 ----
    float qn = fmaf(rn0, rn0, rn1 * rn1);
    float qm = fmaf(rm0, rm0, rm1 * rm1);
#pragma unroll
    for (int o = 16; o; o >>= 1) {
        qn += __shfl_xor_sync(0xffffffffu, qn, o);
        qm += __shfl_xor_sync(0xffffffffu, qm, o);
    }
    float inr = 1.f / fmaxf(sqrtf(qn), 1e-12f);
    float imr = 1.f / fmaxf(sqrtf(qm), 1e-12f);

    size_t snb = (size_t)gw * 256 + (size_t)(layer + 1) * 64;
    size_t smb = (size_t)m * 256 + (size_t)(layer + 1) * 64;
    rds[snb + lane] = rn0 * inr;  rds[snb + 32 + lane] = rn1 * inr;
    rds[smb + lane] = rm0 * imr;  rds[smb + 32 + lane] = rm1 * imr;

    // ---- cur update (skip on last layer: never read again) ----
    size_t bn = (size_t)gw * 64;
    size_t bm = (size_t)m * 64;
    if (layer < 2) {
        curB[bn + lane]      = 0.5f * pn0 + 0.5f * rn0;
        curB[bn + 32 + lane] = 0.5f * pn1 + 0.5f * rn1;
        curB[bm + lane]      = 0.5f * pm0 + 0.5f * rm0;
        curB[bm + 32 + lane] = 0.5f * pm1 + 0.5f * rm1;
    }

    // ---- l2n(d0)/l2n(s0) accumulated into drugE/disE ----
    float tn = fmaf(pn0, pn0, pn1 * pn1);
    float tm = fmaf(pm0, pm0, pm1 * pm1);
#pragma unroll
    for (int o = 16; o; o >>= 1) {
        tn += __shfl_xor_sync(0xffffffffu, tn, o);
        tm += __shfl_xor_sync(0xffffffffu, tm, o);
    }
    float ipn = 1.f / fmaxf(sqrtf(tn), 1e-12f);
    float ipm = 1.f / fmaxf(sqrtf(tm), 1e-12f);

    eD[bn + lane]      += pn0 * ipn;
    eD[bn + 32 + lane] += pn1 * ipn;
    eS[bn + lane]      += pm0 * ipm;
    eS[bn + 32 + lane] += pm1 * ipm;
}

// ---------------- final: scale means, combine with embeddings ----------------
__global__ void final_kernel(const float* __restrict__ de, const float* __restrict__ se,
                             float* __restrict__ out) {
    size_t i = (size_t)blockIdx.x * blockDim.x + threadIdx.x;
    if (i == 0) out[OFF_LOSS] = 0.f;
    if (i < 6400000) {
        float E = out[OFF_DRUGE + i] * 0.25f;
        float emb = de[i];
        out[OFF_DRUGE + i] = E;
        out[OFF_DRUGALL + i] = 0.5f * emb + 0.5f * E;
        out[OFF_RDDRUG + i] = emb;
    } else if (i < 12800000) {
        size_t j = i - 6400000;
        float E = out[OFF_DISE + j] * 0.25f;
        float emb = se[j];
        out[OFF_DISE + j] = E;
        out[OFF_DISALL + j] = 0.5f * emb + 0.5f * E;
        out[OFF_RDDIS + j] = emb;
    }
}

// ---------------- host-side threefry for key folding ----------------
static inline void tf_host(uint32_t k0, uint32_t k1, uint32_t* px0, uint32_t* px1) {
    uint32_t x0 = *px0, x1 = *px1;
    uint32_t k2 = k0 ^ k1 ^ 0x1BD11BDAu;
#define HROT(r) { x0 += x1; x1 = (x1 << r) | (x1 >> (32 - r)); x1 ^= x0; }
    x0 += k0; x1 += k1;
    HROT(13) HROT(15) HROT(26) HROT(6)
    x0 += k1; x1 += k2 + 1u;
    HROT(17) HROT(29) HROT(16) HROT(24)
    x0 += k2; x1 += k0 + 2u;
    HROT(13) HROT(15) HROT(26) HROT(6)
    x0 += k0; x1 += k1 + 3u;
    HROT(17) HROT(29) HROT(16) HROT(24)
    x0 += k1; x1 += k2 + 4u;
    HROT(13) HROT(15) HROT(26) HROT(6)
    x0 += k2; x1 += k0 + 5u;
#undef HROT
    *px0 = x0; *px1 = x1;
}

extern "C" void kernel_launch(void* const* d_in, const int* in_sizes, int n_in,
                              void* d_out, int out_size) {
    const float* drug_emb = (const float*)d_in[0];
    const float* dis_emb  = (const float*)d_in[1];
    const float* Wr = (const float*)d_in[2];
    const float* br = (const float*)d_in[3];
    const float* Wd = (const float*)d_in[4];
    const float* bd = (const float*)d_in[5];
    const int*   rr_row = (const int*)d_in[6];
    const int*   rr_col = (const int*)d_in[7];
    const float* rr_val = (const float*)d_in[8];
    const int*   dd_row = (const int*)d_in[9];
    const int*   dd_col = (const int*)d_in[10];
    const float* dd_val = (const float*)d_in[11];
    const int*   rd_row = (const int*)d_in[12];
    const int*   rd_col = (const int*)d_in[13];
    const float* rd_val = (const float*)d_in[14];
    float* out = (float*)d_out;

    float *G, *curA, *curB, *deg;
    int2 *csr; int *cnt, *rptr, *cursor, *bsum, *bscan;
    cudaGetSymbolAddress((void**)&G,     g_G);
    cudaGetSymbolAddress((void**)&curA,  g_curA);
    cudaGetSymbolAddress((void**)&curB,  g_curB);
    cudaGetSymbolAddress((void**)&deg,   g_deg);
    cudaGetSymbolAddress((void**)&csr,   g_csr);
    cudaGetSymbolAddress((void**)&cnt,   g_cnt);
    cudaGetSymbolAddress((void**)&rptr,  g_rptr);
    cudaGetSymbolAddress((void**)&cursor,g_cursor);
    cudaGetSymbolAddress((void**)&bsum,  g_bsum);
    cudaGetSymbolAddress((void**)&bscan, g_bscan);

    // ---- one-time per launch: degrees + CSR build (graph-invariant) ----
    cudaMemsetAsync(deg, 0, 800000 * sizeof(float), 0);
    cudaMemsetAsync(cnt, 0, 400000 * sizeof(int), 0);

    deghist_kernel<<<(EDG_RR + 255) / 256, 256>>>(rr_row, rr_col, rr_val, EDG_RR,
                                                  deg + DRR_R, deg + DRR_C, cnt + CNT_RR);
    deghist_kernel<<<(EDG_DD + 255) / 256, 256>>>(dd_row, dd_col, dd_val, EDG_DD,
                                                  deg + DDD_R, deg + DDD_C, cnt + CNT_DD);
    deghist_kernel<<<(EDG_RD + 255) / 256, 256>>>(rd_row, rd_col, rd_val, EDG_RD,
                                                  deg + DRD_R, deg + DRD_C, cnt + CNT_RD);

    // global exclusive scan of all 400000 counts -> global CSR offsets
    scan1_kernel<<<SCAN_NB, 1024>>>(cnt, rptr, bsum);
    scan2_kernel<<<1, 256>>>(bsum, bscan);
    scan3_kernel<<<(SCAN_N + 256) / 256, 256>>>(rptr, cursor, bscan);

    fill_csr<<<(EDG_RR + 255) / 256, 256>>>(rr_row, rr_col, rr_val, deg + DRR_R, deg + DRR_C,
                                            cursor + CNT_RR, csr, EDG_RR);
    fill_csr<<<(EDG_DD + 255) / 256, 256>>>(dd_row, dd_col, dd_val, deg + DDD_R, deg + DDD_C,
                                            cursor + CNT_DD, csr, EDG_DD);
    fill_csr<<<(EDG_RD + 255) / 256, 256>>>(rd_row, rd_col, rd_val, deg + DRD_R, deg + DRD_C,
                                            cursor + CNT_RD, csr, EDG_RD);

    // ---- init: gates, curA = raw emb, rd_stack slice 0, drugE/disE accumulators ----
    init_kernel<<<NRD / 4, 256>>>(drug_emb, dis_emb, Wr, br, Wd, bd,
                                  G, curA, out + OFF_DRUGE, out + OFF_DISE, out + OFF_RDSTACK);

    // ---- fused layers ----
    float* bufs[2] = { curA, curB };
    for (int i = 0; i < 3; i++) {
        uint32_t lk0 = 0u, lk1 = (uint32_t)i;
        tf_host(0u, 1u, &lk0, &lk1);           // fold_in(key(1), i)
        const float* ca = bufs[i & 1];
        float*       cb = bufs[(i + 1) & 1];
        const float* srcPD = (i == 0) ? G : ca;
        layer_kernel<<<(DRUGN * 32 + 255) / 256, 256>>>(rptr, csr, srcPD, ca, cb,
            out + OFF_DRUGE, out + OFF_DISE, out + OFF_RDSTACK, i, lk0, lk1);
    }

    final_kernel<<<(12800000 + 255) / 256, 256>>>(drug_emb, dis_emb, out);
}

// round 13
// speedup vs baseline: 1.5102x; 1.0581x over previous
#include <cuda_runtime.h>
#include <stdint.h>
#include <stddef.h>

// Problem constants
#define DRUGN   100000
#define DISN    100000
#define NRD     200000
#define HIDN    64
#define EDG_RR  1600000
#define EDG_DD  1600000
#define EDG_RD  3200000
#define E_TOT   6400000
#define HBITS   6400000u     // flat-index offset of dis rows (100000*64)
#define EPSF    0.1f

// Output packing (float32), tuple order:
// drugE, disE, drugAll, disAll, rd_drug, rd_dis, meta_reg_loss, rd_stack
// NOTE: OFF_RDSTACK is ODD -> rd_stack is only 4-byte aligned; never use
// vector (float2/float4) accesses on the rds pointer.
static const size_t OFF_DRUGE   = 0;
static const size_t OFF_DISE    = 6400000;
static const size_t OFF_DRUGALL = 12800000;
static const size_t OFF_DISALL  = 19200000;
static const size_t OFF_RDDRUG  = 25600000;
static const size_t OFF_RDDIS   = 32000000;
static const size_t OFF_LOSS    = 38400000;
static const size_t OFF_RDSTACK = 38400001;

// Scratch (static device arrays: no runtime allocation allowed)
__device__ float g_G   [(size_t)NRD * HIDN];  // gated init (rr0 | dd0)
__device__ float g_curA[(size_t)NRD * HIDN];  // cur ping
__device__ float g_curB[(size_t)NRD * HIDN];  // cur pong
__device__ float g_deg[800000];               // degree sums: 6 slices
__device__ int2  g_csr[E_TOT];                // packed (col, w) per edge, global CSR order
__device__ int   g_cnt[400000];               // row counts: rr|dd|rd (contiguous)
__device__ int   g_rptr[400001];              // GLOBAL row pointers (exclusive scan of cnt)
__device__ int   g_cursor[400001];            // scatter cursors
__device__ int   g_bsum[256];                 // per-block sums for multi-block scan

// count/rptr slices (global scan makes edge offsets global automatically)
#define CNT_RR 0
#define CNT_DD 100000
#define CNT_RD 200000
// deg slices
#define DRR_R 0
#define DRR_C 100000
#define DDD_R 200000
#define DDD_C 300000
#define DRD_R 400000
#define DRD_C 600000

#define SCAN_N    400000
#define SCAN_BLK  2048
#define SCAN_NB   ((SCAN_N + SCAN_BLK - 1) / SCAN_BLK)   // 196

// ---------------- threefry2x32 (bit-exact JAX core) ----------------
#define TFROUND(x0,x1,r) { x0 += x1; x1 = __funnelshift_l(x1,x1,r); x1 ^= x0; }

__device__ __forceinline__ void tf2x32(uint32_t k0, uint32_t k1, uint32_t &x0, uint32_t &x1) {
    uint32_t k2 = k0 ^ k1 ^ 0x1BD11BDAu;
    x0 += k0; x1 += k1;
    TFROUND(x0,x1,13) TFROUND(x0,x1,15) TFROUND(x0,x1,26) TFROUND(x0,x1,6)
    x0 += k1; x1 += k2 + 1u;
    TFROUND(x0,x1,17) TFROUND(x0,x1,29) TFROUND(x0,x1,16) TFROUND(x0,x1,24)
    x0 += k2; x1 += k0 + 2u;
    TFROUND(x0,x1,13) TFROUND(x0,x1,15) TFROUND(x0,x1,26) TFROUND(x0,x1,6)
    x0 += k0; x1 += k1 + 3u;
    TFROUND(x0,x1,17) TFROUND(x0,x1,29) TFROUND(x0,x1,16) TFROUND(x0,x1,24)
    x0 += k1; x1 += k2 + 4u;
    TFROUND(x0,x1,13) TFROUND(x0,x1,15) TFROUND(x0,x1,26) TFROUND(x0,x1,6)
    x0 += k2; x1 += k0 + 5u;
}

// Partitionable-threefry random bits: counter (0, f); bits = y0 ^ y1.
__device__ __forceinline__ uint32_t tf_bits32(uint32_t k0, uint32_t k1, uint32_t f) {
    uint32_t x0 = 0u, x1 = f;
    tf2x32(k0, k1, x0, x1);
    return x0 ^ x1;
}

__device__ __forceinline__ float u01(uint32_t b) {
    return __uint_as_float((b >> 9) | 0x3f800000u) - 1.0f;
}
__device__ __forceinline__ float fsgn(float x) {
    return (x > 0.f) ? 1.f : ((x < 0.f) ? -1.f : 0.f);
}

// ---------------- init: gated GEMM + buffer init + scratch zeroing ----------------
// Launch 0. Also zeroes deg/cnt (consumed by the NEXT kernel, so ordering is safe).
__global__ void init_kernel(const float* __restrict__ de, const float* __restrict__ se,
                            const float* __restrict__ Wr, const float* __restrict__ br,
                            const float* __restrict__ Wd, const float* __restrict__ bd,
                            float* __restrict__ G, float* __restrict__ cur,
                            float* __restrict__ eD, float* __restrict__ eS,
                            float* __restrict__ rds,
                            float* __restrict__ deg, int* __restrict__ cnt) {
    __shared__ float sW[64 * 64];
    __shared__ float sb[64];
    __shared__ float sx[4][64];

    // grid-stride zeroing of scratch (50000 blocks x 256 threads = 12.8M threads)
    int gtid = blockIdx.x * 256 + threadIdx.x;
    if (gtid < 800000) deg[gtid] = 0.f;
    if (gtid < 400000) cnt[gtid] = 0;

    bool isDis = (blockIdx.x >= (DRUGN / 4));
    const float* W = isDis ? Wd : Wr;
    const float* b = isDis ? bd : br;
    for (int t = threadIdx.x; t < 4096; t += blockDim.x) sW[t] = W[t];
    if (threadIdx.x < 64) sb[threadIdx.x] = b[threadIdx.x];

    int local = threadIdx.x >> 6;             // 0..3
    int j     = threadIdx.x & 63;             // output column
    int n = blockIdx.x * 4 + local;           // node 0..NRD-1
    const float* emb = isDis ? se : de;
    size_t lrow = isDis ? (size_t)(n - DRUGN) * 64 : (size_t)n * 64;
    sx[local][j] = emb[lrow + j];
    __syncthreads();

    float z = sb[j];
#pragma unroll 16
    for (int k = 0; k < 64; k++) z = fmaf(sx[local][k], sW[k * 64 + j], z);
    float x = sx[local][j];
    float g = x * (1.0f / (1.0f + expf(-z)));

    size_t base = (size_t)n * 64;
    G[base + j]   = g;
    cur[base + j] = x;
    rds[(size_t)n * 256 + j] = x;
    if (!isDis) eD[base + j] = g;
    else        eS[(size_t)(n - DRUGN) * 64 + j] = g;
}

// ---------------- fused degree + row-histogram over ALL 3 graphs ----------------
__global__ void deghist_all(const int* __restrict__ rr_r, const int* __restrict__ rr_c, const float* __restrict__ rr_v,
                            const int* __restrict__ dd_r, const int* __restrict__ dd_c, const float* __restrict__ dd_v,
                            const int* __restrict__ rd_r, const int* __restrict__ rd_c, const float* __restrict__ rd_v,
                            float* __restrict__ deg, int* __restrict__ cnt) {
    int t = blockIdx.x * blockDim.x + threadIdx.x;
    if (t >= E_TOT) return;
    const int* er; const int* ec; const float* ev;
    int e; float* dr; float* dc; int* cn;
    if (t < EDG_RR) {
        e = t; er = rr_r; ec = rr_c; ev = rr_v;
        dr = deg + DRR_R; dc = deg + DRR_C; cn = cnt + CNT_RR;
    } else if (t < EDG_RR + EDG_DD) {
        e = t - EDG_RR; er = dd_r; ec = dd_c; ev = dd_v;
        dr = deg + DDD_R; dc = deg + DDD_C; cn = cnt + CNT_DD;
    } else {
        e = t - EDG_RR - EDG_DD; er = rd_r; ec = rd_c; ev = rd_v;
        dr = deg + DRD_R; dc = deg + DRD_C; cn = cnt + CNT_RD;
    }
    int r = er[e];
    float v = ev[e];
    atomicAdd(&dr[r], v);
    atomicAdd(&dc[ec[e]], v);
    atomicAdd(&cn[r], 1);
}

// ---------------- scan stage 1: per-block local exclusive scan + block sums ----------------
__global__ void scan1_kernel(const int* __restrict__ cnt, int* __restrict__ rptr,
                             int* __restrict__ bsum) {
    __shared__ int ts[1024];
    int t = threadIdx.x;
    int base = blockIdx.x * SCAN_BLK;
    int i0 = base + 2 * t, i1 = i0 + 1;
    int v0 = (i0 < SCAN_N) ? cnt[i0] : 0;
    int v1 = (i1 < SCAN_N) ? cnt[i1] : 0;
    ts[t] = v0 + v1;
    __syncthreads();
    for (int off = 1; off < 1024; off <<= 1) {
        int v = (t >= off) ? ts[t - off] : 0;
        __syncthreads();
        ts[t] += v;
        __syncthreads();
    }
    int excl = (t == 0) ? 0 : ts[t - 1];
    if (i0 < SCAN_N) rptr[i0] = excl;
    if (i1 < SCAN_N) rptr[i1] = excl + v0;
    if (t == 1023) bsum[blockIdx.x] = ts[1023];
}

// ---------------- scan stage 2+3 fused: each block redundantly scans the 196
// block sums (cheap), then adds its offset and writes rptr + cursor ----------------
__global__ void scan23_kernel(int* __restrict__ rptr, int* __restrict__ cursor,
                              const int* __restrict__ bsum) {
    __shared__ int ts[256];
    int t = threadIdx.x;
    ts[t] = (t < SCAN_NB) ? bsum[t] : 0;
    __syncthreads();
    for (int off = 1; off < 256; off <<= 1) {
        int v = (t >= off) ? ts[t - off] : 0;
        __syncthreads();
        ts[t] += v;
        __syncthreads();
    }
    int i = blockIdx.x * blockDim.x + threadIdx.x;
    if (i < SCAN_N) {
        int blk = i / SCAN_BLK;
        int off = (blk == 0) ? 0 : ts[blk - 1];
        int v = rptr[i] + off;
        rptr[i] = v;
        cursor[i] = v;
    } else if (i == SCAN_N) {
        rptr[i] = E_TOT;
        cursor[i] = E_TOT;
    }
}

// ---------------- fused CSR fill over ALL 3 graphs ----------------
__global__ void fill_all(const int* __restrict__ rr_r, const int* __restrict__ rr_c, const float* __restrict__ rr_v,
                         const int* __restrict__ dd_r, const int* __restrict__ dd_c, const float* __restrict__ dd_v,
                         const int* __restrict__ rd_r, const int* __restrict__ rd_c, const float* __restrict__ rd_v,
                         const float* __restrict__ deg, int* __restrict__ cursor,
                         int2* __restrict__ csr) {
    int t = blockIdx.x * blockDim.x + threadIdx.x;
    if (t >= E_TOT) return;
    const int* er; const int* ec; const float* ev;
    int e; const float* dr; const float* dc; int* cu;
    if (t < EDG_RR) {
        e = t; er = rr_r; ec = rr_c; ev = rr_v;
        dr = deg + DRR_R; dc = deg + DRR_C; cu = cursor + CNT_RR;
    } else if (t < EDG_RR + EDG_DD) {
        e = t - EDG_RR; er = dd_r; ec = dd_c; ev = dd_v;
        dr = deg + DDD_R; dc = deg + DDD_C; cu = cursor + CNT_DD;
    } else {
        e = t - EDG_RR - EDG_DD; er = rd_r; ec = rd_c; ev = rd_v;
        dr = deg + DRD_R; dc = deg + DRD_C; cu = cursor + CNT_RD;
    }
    int r = er[e], c = ec[e];
    float w = ev[e] * rsqrtf(fmaxf(dr[r] * dc[c], 1e-12f));
    int pos = atomicAdd(&cu[r], 1);
    int2 pk; pk.x = c; pk.y = __float_as_int(w);
    csr[pos] = pk;
}

// ---------------- CSR row gather (float2 per lane, 4-way unrolled) ----------------
// Lane l accumulates columns 2l and 2l+1 of the output row.
// src rows are 64-float (256B) aligned in scratch buffers -> float2 loads are safe.
__device__ __forceinline__ void accum_row(const int2* __restrict__ ep, int beg, int end,
                                          const float* __restrict__ src, int coff, int lane,
                                          float &o0, float &o1) {
    float a0 = 0.f, a1 = 0.f, b0 = 0.f, b1 = 0.f;
    int e = beg;
    for (; e + 3 < end; e += 4) {
        int2 p0 = ep[e], p1 = ep[e + 1], p2 = ep[e + 2], p3 = ep[e + 3];
        const float2* s0 = (const float2*)(src + (size_t)(p0.x + coff) * 64);
        const float2* s1 = (const float2*)(src + (size_t)(p1.x + coff) * 64);
        const float2* s2 = (const float2*)(src + (size_t)(p2.x + coff) * 64);
        const float2* s3 = (const float2*)(src + (size_t)(p3.x + coff) * 64);
        float2 v0 = s0[lane], v1 = s1[lane], v2 = s2[lane], v3 = s3[lane];
        float w0 = __int_as_float(p0.y), w1 = __int_as_float(p1.y);
        float w2 = __int_as_float(p2.y), w3 = __int_as_float(p3.y);
        a0 = fmaf(w0, v0.x, a0);  a1 = fmaf(w0, v0.y, a1);
        b0 = fmaf(w1, v1.x, b0);  b1 = fmaf(w1, v1.y, b1);
        a0 = fmaf(w2, v2.x, a0);  a1 = fmaf(w2, v2.y, a1);
        b0 = fmaf(w3, v3.x, b0);  b1 = fmaf(w3, v3.y, b1);
    }
    for (; e < end; e++) {
        int2 p = ep[e];
        float w = __int_as_float(p.y);
        const float2* s = (const float2*)(src + (size_t)(p.x + coff) * 64);
        float2 v = s[lane];
        a0 = fmaf(w, v.x, a0);    a1 = fmaf(w, v.y, a1);
    }
    o0 = a0 + b0; o1 = a1 + b1;
}

// ---------------- fused per-layer kernel ----------------
// One warp handles drug row n and dis row m=n+DRUGN; lane l owns columns 2l, 2l+1.
__global__ void layer_kernel(const int* __restrict__ rptr, const int2* __restrict__ csr,
                             const float* __restrict__ srcPD,  // G (layer0) or curA
                             const float* __restrict__ srcR,   // curA
                             float* __restrict__ curB,         // next cur (unused layer 2)
                             float* __restrict__ eD, float* __restrict__ eS,
                             float* __restrict__ rds,
                             int layer, uint32_t k0, uint32_t k1) {
    int gw = (blockIdx.x * blockDim.x + threadIdx.x) >> 5;
    int lane = threadIdx.x & 31;
    if (gw >= DRUGN) return;
    int m = gw + DRUGN;

    // ---- four gathered rows (global CSR offsets) ----
    float pn0, pn1, pm0, pm1, rn0, rn1, rm0, rm1;
    accum_row(csr, rptr[CNT_RR + gw], rptr[CNT_RR + gw + 1], srcPD, 0,     lane, pn0, pn1);
    accum_row(csr, rptr[CNT_DD + gw], rptr[CNT_DD + gw + 1], srcPD, DRUGN, lane, pm0, pm1);
    accum_row(csr, rptr[CNT_RD + gw], rptr[CNT_RD + gw + 1], srcR,  0,     lane, rn0, rn1);
    accum_row(csr, rptr[CNT_RD + m],  rptr[CNT_RD + m + 1],  srcR,  0,     lane, rm0, rm1);

    // ---- noise (partitionable threefry); lane l covers cols 2l, 2l+1 ----
    uint32_t f0 = (uint32_t)gw * 64u + 2u * (uint32_t)lane;
    float un0 = u01(tf_bits32(k0, k1, f0));
    float un1 = u01(tf_bits32(k0, k1, f0 + 1u));
    float um0 = u01(tf_bits32(k0, k1, f0 + HBITS));
    float um1 = u01(tf_bits32(k0, k1, f0 + 1u + HBITS));

    float sn = fmaf(un0, un0, un1 * un1);
    float sm = fmaf(um0, um0, um1 * um1);
#pragma unroll
    for (int o = 16; o; o >>= 1) {
        sn += __shfl_xor_sync(0xffffffffu, sn, o);
        sm += __shfl_xor_sync(0xffffffffu, sm, o);
    }
    float scn = EPSF / fmaxf(sqrtf(sn), 1e-12f);
    float scm = EPSF / fmaxf(sqrtf(sm), 1e-12f);

    rn0 += fsgn(rn0) * un0 * scn;  rn1 += fsgn(rn1) * un1 * scn;
    rm0 += fsgn(rm0) * um0 * scm;  rm1 += fsgn(rm1) * um1 * scm;

    // ---- l2n(r0) -> rd_stack slice layer+1 ----
    float qn = fmaf(rn0, rn0, rn1 * rn1);
    float qm = fmaf(rm0, rm0, rm1 * rm1);
#pragma unroll
    for (int o = 16; o; o >>= 1) {
        qn += __shfl_xor_sync(0xffffffffu, qn, o);
        qm += __shfl_xor_sync(0xffffffffu, qm, o);
    }
    float inr = 1.f / fmaxf(sqrtf(qn), 1e-12f);
    float imr = 1.f / fmaxf(sqrtf(qm), 1e-12f);

    // rds is 4-byte aligned only (odd base offset) -> SCALAR stores.
    size_t snb = (size_t)gw * 256 + (size_t)(layer + 1) * 64 + 2 * lane;
    size_t smb = (size_t)m * 256 + (size_t)(layer + 1) * 64 + 2 * lane;
    rds[snb]     = rn0 * inr;
    rds[snb + 1] = rn1 * inr;
    rds[smb]     = rm0 * imr;
    rds[smb + 1] = rm1 * imr;

    // ---- cur update (skip on last layer: never read again) ----
    size_t bn = (size_t)gw * 64;
    size_t bm = (size_t)m * 64;
    float2 wv;
    if (layer < 2) {
        wv.x = 0.5f * pn0 + 0.5f * rn0;  wv.y = 0.5f * pn1 + 0.5f * rn1;
        ((float2*)(curB + bn))[lane] = wv;
        wv.x = 0.5f * pm0 + 0.5f * rm0;  wv.y = 0.5f * pm1 + 0.5f * rm1;
        ((float2*)(curB + bm))[lane] = wv;
    }

    // ---- l2n(d0)/l2n(s0) accumulated into drugE/disE ----
    float tn = fmaf(pn0, pn0, pn1 * pn1);
    float tm = fmaf(pm0, pm0, pm1 * pm1);
#pragma unroll
    for (int o = 16; o; o >>= 1) {
        tn += __shfl_xor_sync(0xffffffffu, tn, o);
        tm += __shfl_xor_sync(0xffffffffu, tm, o);
    }
    float ipn = 1.f / fmaxf(sqrtf(tn), 1e-12f);
    float ipm = 1.f / fmaxf(sqrtf(tm), 1e-12f);

    float2 ed = ((float2*)(eD + bn))[lane];
    ed.x += pn0 * ipn;  ed.y += pn1 * ipn;
    ((float2*)(eD + bn))[lane] = ed;
    float2 es = ((float2*)(eS + bn))[lane];
    es.x += pm0 * ipm;  es.y += pm1 * ipm;
    ((float2*)(eS + bn))[lane] = es;
}

// ---------------- final: scale means, combine with embeddings ----------------
__global__ void final_kernel(const float* __restrict__ de, const float* __restrict__ se,
                             float* __restrict__ out) {
    size_t i = (size_t)blockIdx.x * blockDim.x + threadIdx.x;
    if (i == 0) out[OFF_LOSS] = 0.f;
    if (i < 6400000) {
        float E = out[OFF_DRUGE + i] * 0.25f;
        float emb = de[i];
        out[OFF_DRUGE + i] = E;
        out[OFF_DRUGALL + i] = 0.5f * emb + 0.5f * E;
        out[OFF_RDDRUG + i] = emb;
    } else if (i < 12800000) {
        size_t j = i - 6400000;
        float E = out[OFF_DISE + j] * 0.25f;
        float emb = se[j];
        out[OFF_DISE + j] = E;
        out[OFF_DISALL + j] = 0.5f * emb + 0.5f * E;
        out[OFF_RDDIS + j] = emb;
    }
}

// ---------------- host-side threefry for key folding ----------------
static inline void tf_host(uint32_t k0, uint32_t k1, uint32_t* px0, uint32_t* px1) {
    uint32_t x0 = *px0, x1 = *px1;
    uint32_t k2 = k0 ^ k1 ^ 0x1BD11BDAu;
#define HROT(r) { x0 += x1; x1 = (x1 << r) | (x1 >> (32 - r)); x1 ^= x0; }
    x0 += k0; x1 += k1;
    HROT(13) HROT(15) HROT(26) HROT(6)
    x0 += k1; x1 += k2 + 1u;
    HROT(17) HROT(29) HROT(16) HROT(24)
    x0 += k2; x1 += k0 + 2u;
    HROT(13) HROT(15) HROT(26) HROT(6)
    x0 += k0; x1 += k1 + 3u;
    HROT(17) HROT(29) HROT(16) HROT(24)
    x0 += k1; x1 += k2 + 4u;
    HROT(13) HROT(15) HROT(26) HROT(6)
    x0 += k2; x1 += k0 + 5u;
#undef HROT
    *px0 = x0; *px1 = x1;
}

extern "C" void kernel_launch(void* const* d_in, const int* in_sizes, int n_in,
                              void* d_out, int out_size) {
    const float* drug_emb = (const float*)d_in[0];
    const float* dis_emb  = (const float*)d_in[1];
    const float* Wr = (const float*)d_in[2];
    const float* br = (const float*)d_in[3];
    const float* Wd = (const float*)d_in[4];
    const float* bd = (const float*)d_in[5];
    const int*   rr_row = (const int*)d_in[6];
    const int*   rr_col = (const int*)d_in[7];
    const float* rr_val = (const float*)d_in[8];
    const int*   dd_row = (const int*)d_in[9];
    const int*   dd_col = (const int*)d_in[10];
    const float* dd_val = (const float*)d_in[11];
    const int*   rd_row = (const int*)d_in[12];
    const int*   rd_col = (const int*)d_in[13];
    const float* rd_val = (const float*)d_in[14];
    float* out = (float*)d_out;

    float *G, *curA, *curB, *deg;
    int2 *csr; int *cnt, *rptr, *cursor, *bsum;
    cudaGetSymbolAddress((void**)&G,     g_G);
    cudaGetSymbolAddress((void**)&curA,  g_curA);
    cudaGetSymbolAddress((void**)&curB,  g_curB);
    cudaGetSymbolAddress((void**)&deg,   g_deg);
    cudaGetSymbolAddress((void**)&csr,   g_csr);
    cudaGetSymbolAddress((void**)&cnt,   g_cnt);
    cudaGetSymbolAddress((void**)&rptr,  g_rptr);
    cudaGetSymbolAddress((void**)&cursor,g_cursor);
    cudaGetSymbolAddress((void**)&bsum,  g_bsum);

    // Launch 0: init (gates, curA, rd_stack slice 0, eD/eS init) + zero deg/cnt
    init_kernel<<<NRD / 4, 256>>>(drug_emb, dis_emb, Wr, br, Wd, bd,
                                  G, curA, out + OFF_DRUGE, out + OFF_DISE,
                                  out + OFF_RDSTACK, deg, cnt);

    // Launch 1: degrees + row histogram (all graphs, one pass)
    deghist_all<<<(E_TOT + 255) / 256, 256>>>(rr_row, rr_col, rr_val,
                                              dd_row, dd_col, dd_val,
                                              rd_row, rd_col, rd_val, deg, cnt);

    // Launches 2-3: global exclusive scan of 400000 counts -> CSR offsets
    scan1_kernel<<<SCAN_NB, 1024>>>(cnt, rptr, bsum);
    scan23_kernel<<<(SCAN_N + 256) / 256, 256>>>(rptr, cursor, bsum);

    // Launch 4: CSR fill (all graphs, one pass)
    fill_all<<<(E_TOT + 255) / 256, 256>>>(rr_row, rr_col, rr_val,
                                           dd_row, dd_col, dd_val,
                                           rd_row, rd_col, rd_val,
                                           deg, cursor, csr);

    // Launches 5-7: fused layers (launch 5 = layer 0 is the ncu-captured kernel)
    float* bufs[2] = { curA, curB };
    for (int i = 0; i < 3; i++) {
        uint32_t lk0 = 0u, lk1 = (uint32_t)i;
        tf_host(0u, 1u, &lk0, &lk1);           // fold_in(key(1), i)
        const float* ca = bufs[i & 1];
        float*       cb = bufs[(i + 1) & 1];
        const float* srcPD = (i == 0) ? G : ca;
        layer_kernel<<<(DRUGN * 32 + 255) / 256, 256>>>(rptr, csr, srcPD, ca, cb,
            out + OFF_DRUGE, out + OFF_DISE, out + OFF_RDSTACK, i, lk0, lk1);
    }

    // Launch 8: finalize outputs
    final_kernel<<<(12800000 + 255) / 256, 256>>>(drug_emb, dis_emb, out);
}